// round 6
// baseline (speedup 1.0000x reference)
#include <cuda_runtime.h>
#include <cuda_bf16.h>
#include <math.h>

#define BATCH 8
#define NPTS  2048
#define KN    16
#define TPB_SCAN 128
#define TILE     128
#define TPB_NRM  128
#define RED_BLKS 32
#define RED_TPB  256

// ---------------- scratch (no allocations allowed) ----------------
__device__ float g_cd0[BATCH * NPTS];          // min_j ||pred_i - gt_j||^2
__device__ float g_cd1[BATCH * NPTS];          // min_i ||gt_j - pred_i||^2
__device__ float g_rep[BATCH * NPTS];          // per-point repulsion partial (4 terms)
__device__ float g_nrm0[BATCH * NPTS * 3];     // PCA normals of pred
__device__ float g_nrm1[BATCH * NPTS * 3];     // PCA normals of gt
__device__ int   g_knn[2 * BATCH * NPTS * KN]; // 16-NN indices (self incl.)
__device__ double g_part[RED_BLKS][4];         // stage-1 reduction partials

// =================== LAPACK single-precision ports =====================
// Faithful ports of the routines jax/XLA-CPU hits for jnp.linalg.eigh on a
// 3x3 f32 symmetric matrix: ssyevd -> ssytd2 + ssteqr(+slaev2,slartg) + sormtr.
// Sign conventions of the eigenvectors come from these routines; we replicate
// them so the sign-sensitive normal-consistency term matches the reference.

__device__ __forceinline__ float slapy2f(float x, float y) {
    float xa = fabsf(x), ya = fabsf(y);
    float w = fmaxf(xa, ya);
    float z = fminf(xa, ya);
    if (z == 0.0f) return w;
    float q = z / w;
    return w * sqrtf(1.0f + q * q);
}

// LAPACK >= 3.10 slartg
__device__ __forceinline__ void slartgf(float f, float g, float& c, float& s, float& r) {
    const float safmin = 1.17549435e-38f;
    const float safmax = 1.0f / 1.17549435e-38f;
    const float rtmin  = 1.0842021725e-19f;     // sqrt(safmin)
    const float rtmax  = 6.5219432e+18f;        // sqrt(safmax/2)
    float f1 = fabsf(f), g1 = fabsf(g);
    if (g == 0.0f) {
        c = 1.0f; s = 0.0f; r = f;
    } else if (f == 0.0f) {
        c = 0.0f; s = copysignf(1.0f, g); r = g1;
    } else {
        float d;
        if (f1 > rtmin && f1 < rtmax && g1 > rtmin && g1 < rtmax) {
            d = sqrtf(f * f + g * g);
            c = f1 / d;
            r = copysignf(d, f);
        } else {
            float u  = fminf(safmax, fmaxf(safmin, fmaxf(f1, g1)));
            float fs = f / u, gs = g / u;
            d = sqrtf(fs * fs + gs * gs);
            c = fabsf(fs) / d;
            r = copysignf(d, f) * u;
        }
        s = g / r;
    }
}

__device__ void slaev2f(float a, float b, float cc,
                        float& rt1, float& rt2, float& cs1, float& sn1) {
    float sm  = a + cc;
    float df  = a - cc;
    float adf = fabsf(df);
    float tb  = b + b;
    float ab  = fabsf(tb);
    float acmx, acmn;
    if (fabsf(a) > fabsf(cc)) { acmx = a;  acmn = cc; }
    else                      { acmx = cc; acmn = a;  }
    float rt;
    if (adf > ab)      { float q = ab / adf; rt = adf * sqrtf(1.0f + q * q); }
    else if (adf < ab) { float q = adf / ab; rt = ab  * sqrtf(1.0f + q * q); }
    else               { rt = ab * sqrtf(2.0f); }
    int sgn1;
    if (sm < 0.0f) {
        rt1 = 0.5f * (sm - rt); sgn1 = -1;
        rt2 = (acmx / rt1) * acmn - (b / rt1) * b;
    } else if (sm > 0.0f) {
        rt1 = 0.5f * (sm + rt); sgn1 = 1;
        rt2 = (acmx / rt1) * acmn - (b / rt1) * b;
    } else {
        rt1 = 0.5f * rt; rt2 = -0.5f * rt; sgn1 = 1;
    }
    int sgn2;
    float cs;
    if (df >= 0.0f) { cs = df + rt; sgn2 = 1; }
    else            { cs = df - rt; sgn2 = -1; }
    float acs = fabsf(cs);
    if (acs > ab) {
        float ct = -tb / cs;
        sn1 = 1.0f / sqrtf(1.0f + ct * ct);
        cs1 = ct * sn1;
    } else {
        if (ab == 0.0f) { cs1 = 1.0f; sn1 = 0.0f; }
        else {
            float tn = -cs / tb;
            cs1 = 1.0f / sqrtf(1.0f + tn * tn);
            sn1 = tn * cs1;
        }
    }
    if (sgn1 == sgn2) { float tn = cs1; cs1 = -sn1; sn1 = tn; }
}

// ssteqr for n=3, compz='I'.  d[1..3], e[1..2], z[1..3][1..3] (1-based).
__device__ void ssteqr3(float d[4], float e[3], float z[4][4]) {
    const float eps    = 5.9604645e-08f;   // slamch('E') single
    const float eps2   = eps * eps;
    const float safmin = 1.17549435e-38f;
    const float safmax = 1.0f / 1.17549435e-38f;
    const float ssfmax = sqrtf(safmax) / 3.0f;
    const float ssfmin = sqrtf(safmin) / eps2;
    const int n = 3;

    for (int i = 1; i <= 3; ++i)
        for (int j = 1; j <= 3; ++j)
            z[i][j] = (i == j) ? 1.0f : 0.0f;

    int nmaxit = n * 30, jtot = 0;
    int l1 = 1;
    int l = 1, m = 1, lsv = 1, lend = 1, lendsv = 1, iscale = 0;
    float anorm = 0.0f, p, g, r, c, s, f, b, rt1, rt2;
    float wc[3], ws[3];

L10:
    if (l1 > n) goto L160;
    if (l1 > 1) e[l1 - 1] = 0.0f;
    if (l1 <= n - 1) {
        for (m = l1; m <= n - 1; ++m) {
            float tst = fabsf(e[m]);
            if (tst == 0.0f) goto L30;
            if (tst <= (sqrtf(fabsf(d[m])) * sqrtf(fabsf(d[m + 1]))) * eps) {
                e[m] = 0.0f;
                goto L30;
            }
        }
    }
    m = n;
L30:
    l = l1; lsv = l; lend = m; lendsv = lend; l1 = m + 1;
    if (lend == l) goto L10;

    anorm = 0.0f;
    for (int i = l; i <= lend; ++i)     anorm = fmaxf(anorm, fabsf(d[i]));
    for (int i = l; i <= lend - 1; ++i) anorm = fmaxf(anorm, fabsf(e[i]));
    iscale = 0;
    if (anorm == 0.0f) goto L10;
    if (anorm > ssfmax) {
        iscale = 1;
        float mul = ssfmax / anorm;
        for (int i = l; i <= lend; ++i)     d[i] *= mul;
        for (int i = l; i <= lend - 1; ++i) e[i] *= mul;
    } else if (anorm < ssfmin) {
        iscale = 2;
        float mul = ssfmin / anorm;
        for (int i = l; i <= lend; ++i)     d[i] *= mul;
        for (int i = l; i <= lend - 1; ++i) e[i] *= mul;
    }

    if (fabsf(d[lend]) < fabsf(d[l])) { lend = lsv; l = lendsv; }

    if (lend > l) {
        // ---------------- QL iteration ----------------
L40:
        if (l != lend) {
            for (m = l; m <= lend - 1; ++m) {
                float tst = fabsf(e[m]); tst = tst * tst;
                if (tst <= (eps2 * fabsf(d[m])) * fabsf(d[m + 1]) + safmin) goto L60;
            }
        }
        m = lend;
L60:
        if (m < lend) e[m] = 0.0f;
        p = d[l];
        if (m == l) goto L80;
        if (m == l + 1) {
            slaev2f(d[l], e[l], d[l + 1], rt1, rt2, c, s);
            {
                float ct = c, st = s;
                if (!(ct == 1.0f && st == 0.0f)) {
                    for (int i = 1; i <= 3; ++i) {
                        float temp   = z[i][l + 1];
                        z[i][l + 1]  = ct * temp - st * z[i][l];
                        z[i][l]      = st * temp + ct * z[i][l];
                    }
                }
            }
            d[l] = rt1; d[l + 1] = rt2; e[l] = 0.0f;
            l += 2;
            if (l <= lend) goto L40;
            goto L140;
        }
        if (jtot == nmaxit) goto L140;
        ++jtot;
        g = (d[l + 1] - p) / (2.0f * e[l]);
        r = slapy2f(g, 1.0f);
        g = d[m] - p + (e[l] / (g + copysignf(r, g)));
        s = 1.0f; c = 1.0f; p = 0.0f;
        for (int i = m - 1; i >= l; --i) {
            f = s * e[i]; b = c * e[i];
            slartgf(g, f, c, s, r);
            if (i != m - 1) e[i + 1] = r;
            g = d[i + 1] - p;
            r = (d[i] - g) * s + 2.0f * c * b;
            p = s * r;
            d[i + 1] = g + p;
            g = c * r - b;
            wc[i] = c; ws[i] = -s;
        }
        {
            int mm = m - l + 1;
            for (int j = mm - 1; j >= 1; --j) {   // slasr 'R','V','B'
                float ct = wc[l + j - 1], st = ws[l + j - 1];
                if (!(ct == 1.0f && st == 0.0f)) {
                    for (int i = 1; i <= 3; ++i) {
                        float temp       = z[i][l + j];
                        z[i][l + j]      = ct * temp - st * z[i][l + j - 1];
                        z[i][l + j - 1]  = st * temp + ct * z[i][l + j - 1];
                    }
                }
            }
        }
        d[l] -= p;
        e[l] = g;
        goto L40;
L80:
        d[l] = p;
        ++l;
        if (l <= lend) goto L40;
        goto L140;
    } else {
        // ---------------- QR iteration ----------------
L90:
        if (l != lend) {
            for (m = l; m >= lend + 1; --m) {
                float tst = fabsf(e[m - 1]); tst = tst * tst;
                if (tst <= (eps2 * fabsf(d[m])) * fabsf(d[m - 1]) + safmin) goto L110;
            }
        }
        m = lend;
L110:
        if (m > lend) e[m - 1] = 0.0f;
        p = d[l];
        if (m == l) goto L130;
        if (m == l - 1) {
            slaev2f(d[l - 1], e[l - 1], d[l], rt1, rt2, c, s);
            {
                float ct = c, st = s;
                if (!(ct == 1.0f && st == 0.0f)) {
                    for (int i = 1; i <= 3; ++i) {
                        float temp  = z[i][l];
                        z[i][l]     = ct * temp - st * z[i][l - 1];
                        z[i][l - 1] = st * temp + ct * z[i][l - 1];
                    }
                }
            }
            d[l - 1] = rt1; d[l] = rt2; e[l - 1] = 0.0f;
            l -= 2;
            if (l >= lend) goto L90;
            goto L140;
        }
        if (jtot == nmaxit) goto L140;
        ++jtot;
        g = (d[l - 1] - p) / (2.0f * e[l - 1]);
        r = slapy2f(g, 1.0f);
        g = d[m] - p + (e[l - 1] / (g + copysignf(r, g)));
        s = 1.0f; c = 1.0f; p = 0.0f;
        for (int i = m; i <= l - 1; ++i) {
            f = s * e[i]; b = c * e[i];
            slartgf(g, f, c, s, r);
            if (i != m) e[i - 1] = r;
            g = d[i] - p;
            r = (d[i + 1] - g) * s + 2.0f * c * b;
            p = s * r;
            d[i] = g + p;
            g = c * r - b;
            wc[i] = c; ws[i] = s;
        }
        {
            int mm = l - m + 1;
            for (int j = 1; j <= mm - 1; ++j) {   // slasr 'R','V','F'
                float ct = wc[m + j - 1], st = ws[m + j - 1];
                if (!(ct == 1.0f && st == 0.0f)) {
                    for (int i = 1; i <= 3; ++i) {
                        float temp       = z[i][m + j];
                        z[i][m + j]      = ct * temp - st * z[i][m + j - 1];
                        z[i][m + j - 1]  = st * temp + ct * z[i][m + j - 1];
                    }
                }
            }
        }
        d[l] -= p;
        e[l - 1] = g;
        goto L90;
L130:
        d[l] = p;
        --l;
        if (l >= lend) goto L90;
        goto L140;
    }

L140:
    if (iscale == 1) {
        float mul = anorm / ssfmax;
        for (int i = lsv; i <= lendsv; ++i)     d[i] *= mul;
        for (int i = lsv; i <= lendsv - 1; ++i) e[i] *= mul;
    } else if (iscale == 2) {
        float mul = anorm / ssfmin;
        for (int i = lsv; i <= lendsv; ++i)     d[i] *= mul;
        for (int i = lsv; i <= lendsv - 1; ++i) e[i] *= mul;
    }
    if (jtot < nmaxit) goto L10;
    goto L160;

L160:
    // sort ascending, swap eigenvector columns (no sign changes)
    for (int ii = 2; ii <= n; ++ii) {
        int i = ii - 1, k = i;
        float pp = d[i];
        for (int j = ii; j <= n; ++j)
            if (d[j] < pp) { k = j; pp = d[j]; }
        if (k != i) {
            d[k] = d[i]; d[i] = pp;
            for (int rr = 1; rr <= 3; ++rr) {
                float t = z[rr][i]; z[rr][i] = z[rr][k]; z[rr][k] = t;
            }
        }
    }
}

// ssyevd('V','L') for 3x3: ssytd2 + ssteqr + sormtr; return eigvec of smallest ev.
// cov = {a00, a10, a20, a11, a21, a22} (lower triangle)
__device__ void eigvec_smallest3(const float cov[6], float nrm[3]) {
    float a00 = cov[0], a10 = cov[1], a20 = cov[2];
    float a11 = cov[3], a21 = cov[4], a22 = cov[5];

    // slarfg(2, alpha=a10, x=a20)
    float tau1, beta, v2 = 0.0f;
    float xnorm = fabsf(a20);
    if (xnorm == 0.0f) {
        tau1 = 0.0f; beta = a10;
    } else {
        beta = -copysignf(slapy2f(a10, xnorm), a10);
        tau1 = (beta - a10) / beta;
        v2   = a20 / (a10 - beta);
    }
    float e0 = beta;
    if (tau1 != 0.0f) {
        float x0 = tau1 * (a11 + a21 * v2);
        float x1 = tau1 * (a21 + a22 * v2);
        float al = -0.5f * tau1 * (x0 + x1 * v2);
        x0 += al; x1 += al * v2;
        a11 = a11 - x0 - x0;
        a21 = a21 - v2 * x0 - x1;
        a22 = a22 - v2 * x1 - v2 * x1;
    }
    float d[4] = {0.0f, a00, a11, a22};
    float e[3] = {0.0f, e0, a21};
    float z[4][4];
    ssteqr3(d, e, z);

    // sormtr: apply H1 = I - tau*v*v' (rows 2..3) to column 1
    float z1 = z[1][1], z2 = z[2][1], z3 = z[3][1];
    if (tau1 != 0.0f) {
        float w = z2 + v2 * z3;
        z2 -= tau1 * w;
        z3 -= tau1 * w * v2;
    }
    nrm[0] = z1; nrm[1] = z2; nrm[2] = z3;
}

// ========================= scan kernel ===============================

// stable ripple insert (ascending); caller guarantees cd < key[KN-1].
// strict '<' reproduces jax.lax.top_k tie-breaking (earlier index wins).
__device__ __forceinline__ void insert16(float (&key)[KN], int (&kid)[KN],
                                          float cd, int ci) {
    bool carry = true;
#pragma unroll
    for (int k = KN - 1; k > 0; --k) {
        bool mv = carry && (cd < key[k - 1]);
        float nk = mv ? key[k - 1] : cd;
        int   ni = mv ? kid[k - 1] : ci;
        if (carry) { key[k] = nk; kid[k] = ni; }
        carry = mv;
    }
    if (carry) { key[0] = cd; kid[0] = ci; }
}

__global__ void __launch_bounds__(TPB_SCAN) scan_kernel(
    const float* __restrict__ pred, const float* __restrict__ gt) {
    const int side = blockIdx.z;                 // 0: own=pred, 1: own=gt
    const float* own = side ? gt : pred;
    const float* oth = side ? pred : gt;
    const int b = blockIdx.y;
    const int i = blockIdx.x * TPB_SCAN + threadIdx.x;
    const float* P = own + (size_t)b * NPTS * 3;
    const float* Q = oth + (size_t)b * NPTS * 3;

    const float px = P[i * 3 + 0], py = P[i * 3 + 1], pz = P[i * 3 + 2];
    const float pn = px * px + py * py + pz * pz;

    __shared__ float4 s[TILE];

    float key[KN]; int kid[KN];
#pragma unroll
    for (int k = 0; k < KN; ++k) { key[k] = __int_as_float(0x7f800000); kid[k] = 0; }

    // ---- same-cloud 16-NN (self included): chunk-of-8 candidate filter ----
    for (int tile = 0; tile < NPTS; tile += TILE) {
        __syncthreads();
        {
            int j = tile + threadIdx.x;
            float qx = P[j * 3 + 0], qy = P[j * 3 + 1], qz = P[j * 3 + 2];
            s[threadIdx.x] = make_float4(qx, qy, qz, qx * qx + qy * qy + qz * qz);
        }
        __syncthreads();
#pragma unroll 2
        for (int t0 = 0; t0 < TILE; t0 += 8) {
            float d2v[8];
#pragma unroll
            for (int u = 0; u < 8; ++u) {
                float4 q = s[t0 + u];
                float dot = px * q.x + py * q.y + pz * q.z;
                d2v[u] = (pn + q.w) - 2.0f * dot;
            }
            float m0 = fminf(d2v[0], d2v[1]), m1 = fminf(d2v[2], d2v[3]);
            float m2 = fminf(d2v[4], d2v[5]), m3 = fminf(d2v[6], d2v[7]);
            float m = fminf(fminf(m0, m1), fminf(m2, m3));
            if (m < key[KN - 1]) {
                // rare path: in-order inserts keep results identical
#pragma unroll
                for (int u = 0; u < 8; ++u)
                    if (d2v[u] < key[KN - 1]) insert16(key, kid, d2v[u], tile + t0 + u);
            }
        }
    }

    // ---- chamfer: min squared distance to the other cloud (branchless) ----
    float cm[8];
#pragma unroll
    for (int u = 0; u < 8; ++u) cm[u] = __int_as_float(0x7f800000);
    for (int tile = 0; tile < NPTS; tile += TILE) {
        __syncthreads();
        {
            int j = tile + threadIdx.x;
            float qx = Q[j * 3 + 0], qy = Q[j * 3 + 1], qz = Q[j * 3 + 2];
            s[threadIdx.x] = make_float4(qx, qy, qz, qx * qx + qy * qy + qz * qz);
        }
        __syncthreads();
#pragma unroll 2
        for (int t0 = 0; t0 < TILE; t0 += 8) {
#pragma unroll
            for (int u = 0; u < 8; ++u) {
                float4 q = s[t0 + u];
                float dot = px * q.x + py * q.y + pz * q.z;
                float d2 = (pn + q.w) - 2.0f * dot;
                cm[u] = fminf(cm[u], d2);
            }
        }
    }
    float cmin = fminf(fminf(fminf(cm[0], cm[1]), fminf(cm[2], cm[3])),
                       fminf(fminf(cm[4], cm[5]), fminf(cm[6], cm[7])));

    // ---- repulsion: nearest 4 excluding self (list entries 1..4) ----
    float rep = 0.0f;
#pragma unroll
    for (int k = 1; k <= 4; ++k) {
        float dd = sqrtf(fmaxf(key[k], 1e-12f));
        rep += fmaxf(0.02f - dd, 0.0f);
    }

    const int gidx = b * NPTS + i;
    if (side == 0) {
        g_cd0[gidx] = cmin;
        g_rep[gidx] = rep;
    } else {
        g_cd1[gidx] = cmin;
    }
    int* knn = g_knn + ((size_t)(side * BATCH + b) * NPTS + i) * KN;
#pragma unroll
    for (int k = 0; k < KN; ++k) knn[k] = kid[k];
}

// ===================== normals kernel (separate for occupancy) =========
__global__ void __launch_bounds__(TPB_NRM) normals_kernel(
    const float* __restrict__ pred, const float* __restrict__ gt) {
    const int side = blockIdx.z;
    const int b = blockIdx.y;
    const int i = blockIdx.x * TPB_NRM + threadIdx.x;
    const float* P = (side ? gt : pred) + (size_t)b * NPTS * 3;
    const int* knn = g_knn + ((size_t)(side * BATCH + b) * NPTS + i) * KN;

    float nbx[KN], nby[KN], nbz[KN];
#pragma unroll
    for (int k = 0; k < KN; ++k) {
        int j = knn[k];
        nbx[k] = P[j * 3 + 0]; nby[k] = P[j * 3 + 1]; nbz[k] = P[j * 3 + 2];
    }
    float mx = 0.0f, my = 0.0f, mz = 0.0f;
#pragma unroll
    for (int k = 0; k < KN; ++k) { mx += nbx[k]; my += nby[k]; mz += nbz[k]; }
    mx *= (1.0f / KN); my *= (1.0f / KN); mz *= (1.0f / KN);
    float cxx = 0, cxy = 0, cxz = 0, cyy = 0, cyz = 0, czz = 0;
#pragma unroll
    for (int k = 0; k < KN; ++k) {
        float dx = nbx[k] - mx, dy = nby[k] - my, dz = nbz[k] - mz;
        cxx += dx * dx; cxy += dx * dy; cxz += dx * dz;
        cyy += dy * dy; cyz += dy * dz; czz += dz * dz;
    }
    const float invK = 1.0f / KN;
    float cov[6] = {cxx * invK, cxy * invK, cxz * invK,
                    cyy * invK, cyz * invK, czz * invK};
    float nrm[3];
    eigvec_smallest3(cov, nrm);

    float* dst = (side == 0 ? g_nrm0 : g_nrm1) + (size_t)(b * NPTS + i) * 3;
    dst[0] = nrm[0]; dst[1] = nrm[1]; dst[2] = nrm[2];
}

// ---- deterministic two-stage reduction (fixed order, no float atomics) ----
__global__ void __launch_bounds__(RED_TPB) reduce_stage1_kernel() {
    __shared__ double sh0[RED_TPB], sh1[RED_TPB], sh2[RED_TPB], sh3[RED_TPB];
    const int tid = threadIdx.x;
    const int blk = blockIdx.x;
    const int per_blk = (BATCH * NPTS) / RED_BLKS;   // 512
    const int base = blk * per_blk;
    double c0 = 0.0, c1 = 0.0, rp = 0.0, dt = 0.0;
    for (int off = tid; off < per_blk; off += RED_TPB) {
        int idx = base + off;
        c0 += (double)g_cd0[idx];
        c1 += (double)g_cd1[idx];
        rp += (double)g_rep[idx];
        float dd = g_nrm0[idx * 3 + 0] * g_nrm1[idx * 3 + 0]
                 + g_nrm0[idx * 3 + 1] * g_nrm1[idx * 3 + 1]
                 + g_nrm0[idx * 3 + 2] * g_nrm1[idx * 3 + 2];
        dt += (double)dd;
    }
    sh0[tid] = c0; sh1[tid] = c1; sh2[tid] = rp; sh3[tid] = dt;
    __syncthreads();
    for (int off = RED_TPB / 2; off > 0; off >>= 1) {
        if (tid < off) {
            sh0[tid] += sh0[tid + off];
            sh1[tid] += sh1[tid + off];
            sh2[tid] += sh2[tid + off];
            sh3[tid] += sh3[tid + off];
        }
        __syncthreads();
    }
    if (tid == 0) {
        g_part[blk][0] = sh0[0];
        g_part[blk][1] = sh1[0];
        g_part[blk][2] = sh2[0];
        g_part[blk][3] = sh3[0];
    }
}

__global__ void __launch_bounds__(RED_BLKS) reduce_stage2_kernel(float* __restrict__ out) {
    __shared__ double sh0[RED_BLKS], sh1[RED_BLKS], sh2[RED_BLKS], sh3[RED_BLKS];
    const int tid = threadIdx.x;
    sh0[tid] = g_part[tid][0];
    sh1[tid] = g_part[tid][1];
    sh2[tid] = g_part[tid][2];
    sh3[tid] = g_part[tid][3];
    __syncthreads();
    for (int off = RED_BLKS / 2; off > 0; off >>= 1) {
        if (tid < off) {
            sh0[tid] += sh0[tid + off];
            sh1[tid] += sh1[tid + off];
            sh2[tid] += sh2[tid + off];
            sh3[tid] += sh3[tid + off];
        }
        __syncthreads();
    }
    if (tid == 0) {
        const double inv = 1.0 / (double)(BATCH * NPTS);
        double cd    = (sh0[0] + sh1[0]) * inv;
        double rep   = sh2[0] / ((double)BATCH * NPTS * 4.0);
        double normc = 1.0 - sh3[0] * inv;
        out[0] = (float)(cd + 0.1 * rep + 0.01 * normc);
    }
}

extern "C" void kernel_launch(void* const* d_in, const int* in_sizes, int n_in,
                              void* d_out, int out_size) {
    const float* pred = (const float*)d_in[0];
    const float* gt   = (const float*)d_in[1];
    dim3 grid_scan(NPTS / TPB_SCAN, BATCH, 2);
    scan_kernel<<<grid_scan, TPB_SCAN>>>(pred, gt);
    dim3 grid_nrm(NPTS / TPB_NRM, BATCH, 2);
    normals_kernel<<<grid_nrm, TPB_NRM>>>(pred, gt);
    reduce_stage1_kernel<<<RED_BLKS, RED_TPB>>>();
    reduce_stage2_kernel<<<1, RED_BLKS>>>((float*)d_out);
}

// round 7
// speedup vs baseline: 15.6840x; 15.6840x over previous
#include <cuda_runtime.h>
#include <cuda_bf16.h>
#include <math.h>

#define BATCH 8
#define NPTS  2048
#define KN    16
#define TPB   128
#define TILE  128
#define CAP   96
#define NTH   8
#define RED_BLKS 32
#define RED_TPB  256

// ---------------- scratch (no allocations allowed) ----------------
__device__ float g_cd0[BATCH * NPTS];
__device__ float g_cd1[BATCH * NPTS];
__device__ float g_rep[BATCH * NPTS];
__device__ float g_nrm0[BATCH * NPTS * 3];
__device__ float g_nrm1[BATCH * NPTS * 3];
__device__ float g_thresh[2 * BATCH * NPTS];    // chosen threshold (or -1)
__device__ int   g_knn[2 * BATCH * NPTS * KN];
__device__ double g_part[RED_BLKS][4];

// pinned arithmetic shared by count & collect kernels (must match exactly)
__device__ __forceinline__ float norm2f(float x, float y, float z) {
    return __fmaf_rn(x, x, __fmaf_rn(y, y, __fmul_rn(z, z)));
}
__device__ __forceinline__ float dist2f(float px, float py, float pz, float pn,
                                        float4 q) {
    float dot = __fmaf_rn(px, q.x, __fmaf_rn(py, q.y, __fmul_rn(pz, q.z)));
    return __fmaf_rn(-2.0f, dot, __fadd_rn(pn, q.w));
}
__device__ __forceinline__ float thval(int k) { return 0.006f * (float)(1 << k); }

// =================== LAPACK single-precision ports =====================
// Faithful ports of the routines jax/XLA-CPU hits for jnp.linalg.eigh on a
// 3x3 f32 symmetric matrix (sign conventions must match the reference).

__device__ __forceinline__ float slapy2f(float x, float y) {
    float xa = fabsf(x), ya = fabsf(y);
    float w = fmaxf(xa, ya);
    float z = fminf(xa, ya);
    if (z == 0.0f) return w;
    float q = z / w;
    return w * sqrtf(1.0f + q * q);
}

__device__ __forceinline__ void slartgf(float f, float g, float& c, float& s, float& r) {
    const float safmin = 1.17549435e-38f;
    const float safmax = 1.0f / 1.17549435e-38f;
    const float rtmin  = 1.0842021725e-19f;
    const float rtmax  = 6.5219432e+18f;
    float f1 = fabsf(f), g1 = fabsf(g);
    if (g == 0.0f) {
        c = 1.0f; s = 0.0f; r = f;
    } else if (f == 0.0f) {
        c = 0.0f; s = copysignf(1.0f, g); r = g1;
    } else {
        float d;
        if (f1 > rtmin && f1 < rtmax && g1 > rtmin && g1 < rtmax) {
            d = sqrtf(f * f + g * g);
            c = f1 / d;
            r = copysignf(d, f);
        } else {
            float u  = fminf(safmax, fmaxf(safmin, fmaxf(f1, g1)));
            float fs = f / u, gs = g / u;
            d = sqrtf(fs * fs + gs * gs);
            c = fabsf(fs) / d;
            r = copysignf(d, f) * u;
        }
        s = g / r;
    }
}

__device__ void slaev2f(float a, float b, float cc,
                        float& rt1, float& rt2, float& cs1, float& sn1) {
    float sm  = a + cc;
    float df  = a - cc;
    float adf = fabsf(df);
    float tb  = b + b;
    float ab  = fabsf(tb);
    float acmx, acmn;
    if (fabsf(a) > fabsf(cc)) { acmx = a;  acmn = cc; }
    else                      { acmx = cc; acmn = a;  }
    float rt;
    if (adf > ab)      { float q = ab / adf; rt = adf * sqrtf(1.0f + q * q); }
    else if (adf < ab) { float q = adf / ab; rt = ab  * sqrtf(1.0f + q * q); }
    else               { rt = ab * sqrtf(2.0f); }
    int sgn1;
    if (sm < 0.0f) {
        rt1 = 0.5f * (sm - rt); sgn1 = -1;
        rt2 = (acmx / rt1) * acmn - (b / rt1) * b;
    } else if (sm > 0.0f) {
        rt1 = 0.5f * (sm + rt); sgn1 = 1;
        rt2 = (acmx / rt1) * acmn - (b / rt1) * b;
    } else {
        rt1 = 0.5f * rt; rt2 = -0.5f * rt; sgn1 = 1;
    }
    int sgn2;
    float cs;
    if (df >= 0.0f) { cs = df + rt; sgn2 = 1; }
    else            { cs = df - rt; sgn2 = -1; }
    float acs = fabsf(cs);
    if (acs > ab) {
        float ct = -tb / cs;
        sn1 = 1.0f / sqrtf(1.0f + ct * ct);
        cs1 = ct * sn1;
    } else {
        if (ab == 0.0f) { cs1 = 1.0f; sn1 = 0.0f; }
        else {
            float tn = -cs / tb;
            cs1 = 1.0f / sqrtf(1.0f + tn * tn);
            sn1 = tn * cs1;
        }
    }
    if (sgn1 == sgn2) { float tn = cs1; cs1 = -sn1; sn1 = tn; }
}

__device__ void ssteqr3(float d[4], float e[3], float z[4][4]) {
    const float eps    = 5.9604645e-08f;
    const float eps2   = eps * eps;
    const float safmin = 1.17549435e-38f;
    const float safmax = 1.0f / 1.17549435e-38f;
    const float ssfmax = sqrtf(safmax) / 3.0f;
    const float ssfmin = sqrtf(safmin) / eps2;
    const int n = 3;

    for (int i = 1; i <= 3; ++i)
        for (int j = 1; j <= 3; ++j)
            z[i][j] = (i == j) ? 1.0f : 0.0f;

    int nmaxit = n * 30, jtot = 0;
    int l1 = 1;
    int l = 1, m = 1, lsv = 1, lend = 1, lendsv = 1, iscale = 0;
    float anorm = 0.0f, p, g, r, c, s, f, b, rt1, rt2;
    float wc[3], ws[3];

L10:
    if (l1 > n) goto L160;
    if (l1 > 1) e[l1 - 1] = 0.0f;
    if (l1 <= n - 1) {
        for (m = l1; m <= n - 1; ++m) {
            float tst = fabsf(e[m]);
            if (tst == 0.0f) goto L30;
            if (tst <= (sqrtf(fabsf(d[m])) * sqrtf(fabsf(d[m + 1]))) * eps) {
                e[m] = 0.0f;
                goto L30;
            }
        }
    }
    m = n;
L30:
    l = l1; lsv = l; lend = m; lendsv = lend; l1 = m + 1;
    if (lend == l) goto L10;

    anorm = 0.0f;
    for (int i = l; i <= lend; ++i)     anorm = fmaxf(anorm, fabsf(d[i]));
    for (int i = l; i <= lend - 1; ++i) anorm = fmaxf(anorm, fabsf(e[i]));
    iscale = 0;
    if (anorm == 0.0f) goto L10;
    if (anorm > ssfmax) {
        iscale = 1;
        float mul = ssfmax / anorm;
        for (int i = l; i <= lend; ++i)     d[i] *= mul;
        for (int i = l; i <= lend - 1; ++i) e[i] *= mul;
    } else if (anorm < ssfmin) {
        iscale = 2;
        float mul = ssfmin / anorm;
        for (int i = l; i <= lend; ++i)     d[i] *= mul;
        for (int i = l; i <= lend - 1; ++i) e[i] *= mul;
    }

    if (fabsf(d[lend]) < fabsf(d[l])) { lend = lsv; l = lendsv; }

    if (lend > l) {
L40:
        if (l != lend) {
            for (m = l; m <= lend - 1; ++m) {
                float tst = fabsf(e[m]); tst = tst * tst;
                if (tst <= (eps2 * fabsf(d[m])) * fabsf(d[m + 1]) + safmin) goto L60;
            }
        }
        m = lend;
L60:
        if (m < lend) e[m] = 0.0f;
        p = d[l];
        if (m == l) goto L80;
        if (m == l + 1) {
            slaev2f(d[l], e[l], d[l + 1], rt1, rt2, c, s);
            {
                float ct = c, st = s;
                if (!(ct == 1.0f && st == 0.0f)) {
                    for (int i = 1; i <= 3; ++i) {
                        float temp   = z[i][l + 1];
                        z[i][l + 1]  = ct * temp - st * z[i][l];
                        z[i][l]      = st * temp + ct * z[i][l];
                    }
                }
            }
            d[l] = rt1; d[l + 1] = rt2; e[l] = 0.0f;
            l += 2;
            if (l <= lend) goto L40;
            goto L140;
        }
        if (jtot == nmaxit) goto L140;
        ++jtot;
        g = (d[l + 1] - p) / (2.0f * e[l]);
        r = slapy2f(g, 1.0f);
        g = d[m] - p + (e[l] / (g + copysignf(r, g)));
        s = 1.0f; c = 1.0f; p = 0.0f;
        for (int i = m - 1; i >= l; --i) {
            f = s * e[i]; b = c * e[i];
            slartgf(g, f, c, s, r);
            if (i != m - 1) e[i + 1] = r;
            g = d[i + 1] - p;
            r = (d[i] - g) * s + 2.0f * c * b;
            p = s * r;
            d[i + 1] = g + p;
            g = c * r - b;
            wc[i] = c; ws[i] = -s;
        }
        {
            int mm = m - l + 1;
            for (int j = mm - 1; j >= 1; --j) {
                float ct = wc[l + j - 1], st = ws[l + j - 1];
                if (!(ct == 1.0f && st == 0.0f)) {
                    for (int i = 1; i <= 3; ++i) {
                        float temp       = z[i][l + j];
                        z[i][l + j]      = ct * temp - st * z[i][l + j - 1];
                        z[i][l + j - 1]  = st * temp + ct * z[i][l + j - 1];
                    }
                }
            }
        }
        d[l] -= p;
        e[l] = g;
        goto L40;
L80:
        d[l] = p;
        ++l;
        if (l <= lend) goto L40;
        goto L140;
    } else {
L90:
        if (l != lend) {
            for (m = l; m >= lend + 1; --m) {
                float tst = fabsf(e[m - 1]); tst = tst * tst;
                if (tst <= (eps2 * fabsf(d[m])) * fabsf(d[m - 1]) + safmin) goto L110;
            }
        }
        m = lend;
L110:
        if (m > lend) e[m - 1] = 0.0f;
        p = d[l];
        if (m == l) goto L130;
        if (m == l - 1) {
            slaev2f(d[l - 1], e[l - 1], d[l], rt1, rt2, c, s);
            {
                float ct = c, st = s;
                if (!(ct == 1.0f && st == 0.0f)) {
                    for (int i = 1; i <= 3; ++i) {
                        float temp  = z[i][l];
                        z[i][l]     = ct * temp - st * z[i][l - 1];
                        z[i][l - 1] = st * temp + ct * z[i][l - 1];
                    }
                }
            }
            d[l - 1] = rt1; d[l] = rt2; e[l - 1] = 0.0f;
            l -= 2;
            if (l >= lend) goto L90;
            goto L140;
        }
        if (jtot == nmaxit) goto L140;
        ++jtot;
        g = (d[l - 1] - p) / (2.0f * e[l - 1]);
        r = slapy2f(g, 1.0f);
        g = d[m] - p + (e[l - 1] / (g + copysignf(r, g)));
        s = 1.0f; c = 1.0f; p = 0.0f;
        for (int i = m; i <= l - 1; ++i) {
            f = s * e[i]; b = c * e[i];
            slartgf(g, f, c, s, r);
            if (i != m) e[i - 1] = r;
            g = d[i] - p;
            r = (d[i + 1] - g) * s + 2.0f * c * b;
            p = s * r;
            d[i] = g + p;
            g = c * r - b;
            wc[i] = c; ws[i] = s;
        }
        {
            int mm = l - m + 1;
            for (int j = 1; j <= mm - 1; ++j) {
                float ct = wc[m + j - 1], st = ws[m + j - 1];
                if (!(ct == 1.0f && st == 0.0f)) {
                    for (int i = 1; i <= 3; ++i) {
                        float temp       = z[i][m + j];
                        z[i][m + j]      = ct * temp - st * z[i][m + j - 1];
                        z[i][m + j - 1]  = st * temp + ct * z[i][m + j - 1];
                    }
                }
            }
        }
        d[l] -= p;
        e[l - 1] = g;
        goto L90;
L130:
        d[l] = p;
        --l;
        if (l >= lend) goto L90;
        goto L140;
    }

L140:
    if (iscale == 1) {
        float mul = anorm / ssfmax;
        for (int i = lsv; i <= lendsv; ++i)     d[i] *= mul;
        for (int i = lsv; i <= lendsv - 1; ++i) e[i] *= mul;
    } else if (iscale == 2) {
        float mul = anorm / ssfmin;
        for (int i = lsv; i <= lendsv; ++i)     d[i] *= mul;
        for (int i = lsv; i <= lendsv - 1; ++i) e[i] *= mul;
    }
    if (jtot < nmaxit) goto L10;
    goto L160;

L160:
    for (int ii = 2; ii <= n; ++ii) {
        int i = ii - 1, k = i;
        float pp = d[i];
        for (int j = ii; j <= n; ++j)
            if (d[j] < pp) { k = j; pp = d[j]; }
        if (k != i) {
            d[k] = d[i]; d[i] = pp;
            for (int rr = 1; rr <= 3; ++rr) {
                float t = z[rr][i]; z[rr][i] = z[rr][k]; z[rr][k] = t;
            }
        }
    }
}

__device__ void eigvec_smallest3(const float cov[6], float nrm[3]) {
    float a00 = cov[0], a10 = cov[1], a20 = cov[2];
    float a11 = cov[3], a21 = cov[4], a22 = cov[5];

    float tau1, beta, v2 = 0.0f;
    float xnorm = fabsf(a20);
    if (xnorm == 0.0f) {
        tau1 = 0.0f; beta = a10;
    } else {
        beta = -copysignf(slapy2f(a10, xnorm), a10);
        tau1 = (beta - a10) / beta;
        v2   = a20 / (a10 - beta);
    }
    float e0 = beta;
    if (tau1 != 0.0f) {
        float x0 = tau1 * (a11 + a21 * v2);
        float x1 = tau1 * (a21 + a22 * v2);
        float al = -0.5f * tau1 * (x0 + x1 * v2);
        x0 += al; x1 += al * v2;
        a11 = a11 - x0 - x0;
        a21 = a21 - v2 * x0 - x1;
        a22 = a22 - v2 * x1 - v2 * x1;
    }
    float d[4] = {0.0f, a00, a11, a22};
    float e[3] = {0.0f, e0, a21};
    float z[4][4];
    ssteqr3(d, e, z);

    float z1 = z[1][1], z2 = z[2][1], z3 = z[3][1];
    if (tau1 != 0.0f) {
        float w = z2 + v2 * z3;
        z2 -= tau1 * w;
        z3 -= tau1 * w * v2;
    }
    nrm[0] = z1; nrm[1] = z2; nrm[2] = z3;
}

// ====================== K1: chamfer (branchless) =======================
__global__ void __launch_bounds__(TPB) chamfer_kernel(
    const float* __restrict__ pred, const float* __restrict__ gt) {
    const int side = blockIdx.z;
    const int b = blockIdx.y;
    const int i = blockIdx.x * TPB + threadIdx.x;
    const float* P = (side ? gt : pred) + (size_t)b * NPTS * 3;
    const float* Q = (side ? pred : gt) + (size_t)b * NPTS * 3;

    const float px = P[i * 3 + 0], py = P[i * 3 + 1], pz = P[i * 3 + 2];
    const float pn = norm2f(px, py, pz);

    __shared__ float4 s[TILE];
    float cm[8];
#pragma unroll
    for (int u = 0; u < 8; ++u) cm[u] = __int_as_float(0x7f800000);

    for (int tile = 0; tile < NPTS; tile += TILE) {
        __syncthreads();
        {
            int j = tile + threadIdx.x;
            float qx = Q[j * 3 + 0], qy = Q[j * 3 + 1], qz = Q[j * 3 + 2];
            s[threadIdx.x] = make_float4(qx, qy, qz, norm2f(qx, qy, qz));
        }
        __syncthreads();
#pragma unroll 2
        for (int t0 = 0; t0 < TILE; t0 += 8) {
#pragma unroll
            for (int u = 0; u < 8; ++u)
                cm[u] = fminf(cm[u], dist2f(px, py, pz, pn, s[t0 + u]));
        }
    }
    float cmin = fminf(fminf(fminf(cm[0], cm[1]), fminf(cm[2], cm[3])),
                       fminf(fminf(cm[4], cm[5]), fminf(cm[6], cm[7])));
    int gidx = b * NPTS + i;
    if (side == 0) g_cd0[gidx] = cmin; else g_cd1[gidx] = cmin;
}

// ============ K2: exact counts at 8 thresholds -> pick T* ==============
__global__ void __launch_bounds__(TPB) count_kernel(
    const float* __restrict__ pred, const float* __restrict__ gt) {
    const int side = blockIdx.z;
    const int b = blockIdx.y;
    const int i = blockIdx.x * TPB + threadIdx.x;
    const float* P = (side ? gt : pred) + (size_t)b * NPTS * 3;

    const float px = P[i * 3 + 0], py = P[i * 3 + 1], pz = P[i * 3 + 2];
    const float pn = norm2f(px, py, pz);

    __shared__ float4 s[TILE];
    int c[NTH];
#pragma unroll
    for (int k = 0; k < NTH; ++k) c[k] = 0;

    for (int tile = 0; tile < NPTS; tile += TILE) {
        __syncthreads();
        {
            int j = tile + threadIdx.x;
            float qx = P[j * 3 + 0], qy = P[j * 3 + 1], qz = P[j * 3 + 2];
            s[threadIdx.x] = make_float4(qx, qy, qz, norm2f(qx, qy, qz));
        }
        __syncthreads();
#pragma unroll 4
        for (int t = 0; t < TILE; ++t) {
            float d2 = dist2f(px, py, pz, pn, s[t]);
#pragma unroll
            for (int k = 0; k < NTH; ++k)
                c[k] += (d2 < thval(k)) ? 1 : 0;
        }
    }
    // smallest k with c_k >= 16; valid only if that count fits the buffer
    float tsel = -1.0f;
#pragma unroll
    for (int k = NTH - 1; k >= 0; --k)
        if (c[k] >= KN) tsel = (c[k] <= CAP) ? thval(k) : -1.0f;
    g_thresh[(size_t)(side * BATCH + b) * NPTS + i] = tsel;
}

// ====== K3: predicated collect into smem buffer + stable select ========
// stable ripple insert for the (block-uniform) fallback path only
__device__ __forceinline__ void insert16(float (&key)[KN], int (&kid)[KN],
                                          float cd, int ci) {
    bool carry = true;
#pragma unroll
    for (int k = KN - 1; k > 0; --k) {
        bool mv = carry && (cd < key[k - 1]);
        float nk = mv ? key[k - 1] : cd;
        int   ni = mv ? kid[k - 1] : ci;
        if (carry) { key[k] = nk; kid[k] = ni; }
        carry = mv;
    }
    if (carry) { key[0] = cd; kid[0] = ci; }
}

// dynamic smem layout: float4 tile[TILE] | float d2buf[CAP][TPB] | u16 idxbuf[CAP][TPB]
#define K3_SMEM (TILE * 16 + CAP * TPB * 4 + CAP * TPB * 2)

__global__ void __launch_bounds__(TPB) select_kernel(
    const float* __restrict__ pred, const float* __restrict__ gt) {
    extern __shared__ char sm[];
    float4* s = (float4*)sm;
    float* d2buf = (float*)(sm + TILE * 16);
    unsigned short* idxbuf = (unsigned short*)(sm + TILE * 16 + CAP * TPB * 4);

    const int side = blockIdx.z;
    const int b = blockIdx.y;
    const int tid = threadIdx.x;
    const int i = blockIdx.x * TPB + tid;
    const float* P = (side ? gt : pred) + (size_t)b * NPTS * 3;

    const float px = P[i * 3 + 0], py = P[i * 3 + 1], pz = P[i * 3 + 2];
    const float pn = norm2f(px, py, pz);
    const float T = g_thresh[(size_t)(side * BATCH + b) * NPTS + i];

    // ---- collect pass: predicated append, no branches in hot loop ----
    int cnt = 0;
    for (int tile = 0; tile < NPTS; tile += TILE) {
        __syncthreads();
        {
            int j = tile + threadIdx.x;
            float qx = P[j * 3 + 0], qy = P[j * 3 + 1], qz = P[j * 3 + 2];
            s[threadIdx.x] = make_float4(qx, qy, qz, norm2f(qx, qy, qz));
        }
        __syncthreads();
#pragma unroll 4
        for (int t = 0; t < TILE; ++t) {
            float d2 = dist2f(px, py, pz, pn, s[t]);
            bool take = (d2 < T) && (cnt < CAP);   // T = -1 -> never
            if (take) {                             // tiny predicable body
                d2buf[cnt * TPB + tid] = d2;
                idxbuf[cnt * TPB + tid] = (unsigned short)(tile + t);
                ++cnt;
            }
        }
    }

    float key[KN]; int kid[KN];
    bool fb = (cnt < KN);
    int anyfb = __syncthreads_or(fb ? 1 : 0);

    if (anyfb) {
        // block-uniform fallback: classic insert scan (identical semantics)
#pragma unroll
        for (int k = 0; k < KN; ++k) { key[k] = __int_as_float(0x7f800000); kid[k] = 0; }
        for (int tile = 0; tile < NPTS; tile += TILE) {
            __syncthreads();
            {
                int j = tile + threadIdx.x;
                float qx = P[j * 3 + 0], qy = P[j * 3 + 1], qz = P[j * 3 + 2];
                s[threadIdx.x] = make_float4(qx, qy, qz, norm2f(qx, qy, qz));
            }
            __syncthreads();
            for (int t = 0; t < TILE; ++t) {
                float d2 = dist2f(px, py, pz, pn, s[t]);
                if (d2 < key[KN - 1]) insert16(key, kid, d2, tile + t);
            }
        }
    } else {
        // stable strict-min extraction: 16 rounds over <=CAP smem entries.
        // ascending-slot scan + strict '<' => lowest index wins ties,
        // exactly matching jax.lax.top_k ordering.
#pragma unroll
        for (int r = 0; r < KN; ++r) {
            float best = __int_as_float(0x7f800000);
            int bslot = 0;
            for (int j = 0; j < cnt; ++j) {
                float v = d2buf[j * TPB + tid];
                if (v < best) { best = v; bslot = j; }
            }
            key[r] = best;
            kid[r] = (int)idxbuf[bslot * TPB + tid];
            d2buf[bslot * TPB + tid] = __int_as_float(0x7f800000);
        }
    }

    // ---- repulsion from entries 1..4 (entry 0 = self) ----
    float rep = 0.0f;
#pragma unroll
    for (int k = 1; k <= 4; ++k) {
        float dd = sqrtf(fmaxf(key[k], 1e-12f));
        rep += fmaxf(0.02f - dd, 0.0f);
    }
    if (side == 0) g_rep[b * NPTS + i] = rep;

    int* knn = g_knn + ((size_t)(side * BATCH + b) * NPTS + i) * KN;
#pragma unroll
    for (int k = 0; k < KN; ++k) knn[k] = kid[k];
}

// ===================== K4: normals (PCA eigh) ==========================
__global__ void __launch_bounds__(TPB) normals_kernel(
    const float* __restrict__ pred, const float* __restrict__ gt) {
    const int side = blockIdx.z;
    const int b = blockIdx.y;
    const int i = blockIdx.x * TPB + threadIdx.x;
    const float* P = (side ? gt : pred) + (size_t)b * NPTS * 3;
    const int* knn = g_knn + ((size_t)(side * BATCH + b) * NPTS + i) * KN;

    float nbx[KN], nby[KN], nbz[KN];
#pragma unroll
    for (int k = 0; k < KN; ++k) {
        int j = knn[k];
        nbx[k] = P[j * 3 + 0]; nby[k] = P[j * 3 + 1]; nbz[k] = P[j * 3 + 2];
    }
    float mx = 0.0f, my = 0.0f, mz = 0.0f;
#pragma unroll
    for (int k = 0; k < KN; ++k) { mx += nbx[k]; my += nby[k]; mz += nbz[k]; }
    mx *= (1.0f / KN); my *= (1.0f / KN); mz *= (1.0f / KN);
    float cxx = 0, cxy = 0, cxz = 0, cyy = 0, cyz = 0, czz = 0;
#pragma unroll
    for (int k = 0; k < KN; ++k) {
        float dx = nbx[k] - mx, dy = nby[k] - my, dz = nbz[k] - mz;
        cxx += dx * dx; cxy += dx * dy; cxz += dx * dz;
        cyy += dy * dy; cyz += dy * dz; czz += dz * dz;
    }
    const float invK = 1.0f / KN;
    float cov[6] = {cxx * invK, cxy * invK, cxz * invK,
                    cyy * invK, cyz * invK, czz * invK};
    float nrm[3];
    eigvec_smallest3(cov, nrm);

    float* dst = (side == 0 ? g_nrm0 : g_nrm1) + (size_t)(b * NPTS + i) * 3;
    dst[0] = nrm[0]; dst[1] = nrm[1]; dst[2] = nrm[2];
}

// ---- deterministic two-stage reduction ----
__global__ void __launch_bounds__(RED_TPB) reduce_stage1_kernel() {
    __shared__ double sh0[RED_TPB], sh1[RED_TPB], sh2[RED_TPB], sh3[RED_TPB];
    const int tid = threadIdx.x;
    const int blk = blockIdx.x;
    const int per_blk = (BATCH * NPTS) / RED_BLKS;
    const int base = blk * per_blk;
    double c0 = 0.0, c1 = 0.0, rp = 0.0, dt = 0.0;
    for (int off = tid; off < per_blk; off += RED_TPB) {
        int idx = base + off;
        c0 += (double)g_cd0[idx];
        c1 += (double)g_cd1[idx];
        rp += (double)g_rep[idx];
        float dd = g_nrm0[idx * 3 + 0] * g_nrm1[idx * 3 + 0]
                 + g_nrm0[idx * 3 + 1] * g_nrm1[idx * 3 + 1]
                 + g_nrm0[idx * 3 + 2] * g_nrm1[idx * 3 + 2];
        dt += (double)dd;
    }
    sh0[tid] = c0; sh1[tid] = c1; sh2[tid] = rp; sh3[tid] = dt;
    __syncthreads();
    for (int off = RED_TPB / 2; off > 0; off >>= 1) {
        if (tid < off) {
            sh0[tid] += sh0[tid + off];
            sh1[tid] += sh1[tid + off];
            sh2[tid] += sh2[tid + off];
            sh3[tid] += sh3[tid + off];
        }
        __syncthreads();
    }
    if (tid == 0) {
        g_part[blk][0] = sh0[0];
        g_part[blk][1] = sh1[0];
        g_part[blk][2] = sh2[0];
        g_part[blk][3] = sh3[0];
    }
}

__global__ void __launch_bounds__(RED_BLKS) reduce_stage2_kernel(float* __restrict__ out) {
    __shared__ double sh0[RED_BLKS], sh1[RED_BLKS], sh2[RED_BLKS], sh3[RED_BLKS];
    const int tid = threadIdx.x;
    sh0[tid] = g_part[tid][0];
    sh1[tid] = g_part[tid][1];
    sh2[tid] = g_part[tid][2];
    sh3[tid] = g_part[tid][3];
    __syncthreads();
    for (int off = RED_BLKS / 2; off > 0; off >>= 1) {
        if (tid < off) {
            sh0[tid] += sh0[tid + off];
            sh1[tid] += sh1[tid + off];
            sh2[tid] += sh2[tid + off];
            sh3[tid] += sh3[tid + off];
        }
        __syncthreads();
    }
    if (tid == 0) {
        const double inv = 1.0 / (double)(BATCH * NPTS);
        double cd    = (sh0[0] + sh1[0]) * inv;
        double rep   = sh2[0] / ((double)BATCH * NPTS * 4.0);
        double normc = 1.0 - sh3[0] * inv;
        out[0] = (float)(cd + 0.1 * rep + 0.01 * normc);
    }
}

extern "C" void kernel_launch(void* const* d_in, const int* in_sizes, int n_in,
                              void* d_out, int out_size) {
    const float* pred = (const float*)d_in[0];
    const float* gt   = (const float*)d_in[1];
    cudaFuncSetAttribute(select_kernel,
                         cudaFuncAttributeMaxDynamicSharedMemorySize, K3_SMEM);
    dim3 grid(NPTS / TPB, BATCH, 2);
    chamfer_kernel<<<grid, TPB>>>(pred, gt);
    count_kernel<<<grid, TPB>>>(pred, gt);
    select_kernel<<<grid, TPB, K3_SMEM>>>(pred, gt);
    normals_kernel<<<grid, TPB>>>(pred, gt);
    reduce_stage1_kernel<<<RED_BLKS, RED_TPB>>>();
    reduce_stage2_kernel<<<1, RED_BLKS>>>((float*)d_out);
}

// round 8
// speedup vs baseline: 16.9841x; 1.0829x over previous
#include <cuda_runtime.h>
#include <cuda_bf16.h>
#include <math.h>

#define BATCH 8
#define NPTS  2048
#define KN    16
#define TPB   128
#define TILE  128
#define CAP   96
#define NTH   6
#define SEG   4
#define SEGLEN (NPTS / SEG)
#define RED_BLKS 32
#define RED_TPB  256

// ---------------- scratch (no allocations allowed) ----------------
__device__ float g_cd0[BATCH * NPTS];
__device__ float g_cd1[BATCH * NPTS];
__device__ float g_rep[BATCH * NPTS];
__device__ float g_nrm0[BATCH * NPTS * 3];
__device__ float g_nrm1[BATCH * NPTS * 3];
__device__ float g_thresh[2 * BATCH * NPTS];        // chosen threshold (or -1)
__device__ int   g_knn[2 * BATCH * NPTS * KN];
__device__ float g_cdp[2 * BATCH * NPTS * SEG];     // chamfer partial mins
__device__ uint4 g_cntp[2 * BATCH * NPTS * SEG];    // packed per-seg counts (u16 x6)
__device__ double g_part[RED_BLKS][4];

// pinned arithmetic shared by count & collect (must match exactly)
__device__ __forceinline__ float norm2f(float x, float y, float z) {
    return __fmaf_rn(x, x, __fmaf_rn(y, y, __fmul_rn(z, z)));
}
__device__ __forceinline__ float dist2f(float px, float py, float pz, float pn,
                                        float4 q) {
    float dot = __fmaf_rn(px, q.x, __fmaf_rn(py, q.y, __fmul_rn(pz, q.z)));
    return __fmaf_rn(-2.0f, dot, __fadd_rn(pn, q.w));
}
__device__ __forceinline__ float thval(int k) { return 0.012f * (float)(1 << k); }

// =================== LAPACK single-precision ports =====================
// Faithful ports of the routines jax/XLA-CPU hits for jnp.linalg.eigh on a
// 3x3 f32 symmetric matrix (sign conventions must match the reference).

__device__ __forceinline__ float slapy2f(float x, float y) {
    float xa = fabsf(x), ya = fabsf(y);
    float w = fmaxf(xa, ya);
    float z = fminf(xa, ya);
    if (z == 0.0f) return w;
    float q = z / w;
    return w * sqrtf(1.0f + q * q);
}

__device__ __forceinline__ void slartgf(float f, float g, float& c, float& s, float& r) {
    const float safmin = 1.17549435e-38f;
    const float safmax = 1.0f / 1.17549435e-38f;
    const float rtmin  = 1.0842021725e-19f;
    const float rtmax  = 6.5219432e+18f;
    float f1 = fabsf(f), g1 = fabsf(g);
    if (g == 0.0f) {
        c = 1.0f; s = 0.0f; r = f;
    } else if (f == 0.0f) {
        c = 0.0f; s = copysignf(1.0f, g); r = g1;
    } else {
        float d;
        if (f1 > rtmin && f1 < rtmax && g1 > rtmin && g1 < rtmax) {
            d = sqrtf(f * f + g * g);
            c = f1 / d;
            r = copysignf(d, f);
        } else {
            float u  = fminf(safmax, fmaxf(safmin, fmaxf(f1, g1)));
            float fs = f / u, gs = g / u;
            d = sqrtf(fs * fs + gs * gs);
            c = fabsf(fs) / d;
            r = copysignf(d, f) * u;
        }
        s = g / r;
    }
}

__device__ void slaev2f(float a, float b, float cc,
                        float& rt1, float& rt2, float& cs1, float& sn1) {
    float sm  = a + cc;
    float df  = a - cc;
    float adf = fabsf(df);
    float tb  = b + b;
    float ab  = fabsf(tb);
    float acmx, acmn;
    if (fabsf(a) > fabsf(cc)) { acmx = a;  acmn = cc; }
    else                      { acmx = cc; acmn = a;  }
    float rt;
    if (adf > ab)      { float q = ab / adf; rt = adf * sqrtf(1.0f + q * q); }
    else if (adf < ab) { float q = adf / ab; rt = ab  * sqrtf(1.0f + q * q); }
    else               { rt = ab * sqrtf(2.0f); }
    int sgn1;
    if (sm < 0.0f) {
        rt1 = 0.5f * (sm - rt); sgn1 = -1;
        rt2 = (acmx / rt1) * acmn - (b / rt1) * b;
    } else if (sm > 0.0f) {
        rt1 = 0.5f * (sm + rt); sgn1 = 1;
        rt2 = (acmx / rt1) * acmn - (b / rt1) * b;
    } else {
        rt1 = 0.5f * rt; rt2 = -0.5f * rt; sgn1 = 1;
    }
    int sgn2;
    float cs;
    if (df >= 0.0f) { cs = df + rt; sgn2 = 1; }
    else            { cs = df - rt; sgn2 = -1; }
    float acs = fabsf(cs);
    if (acs > ab) {
        float ct = -tb / cs;
        sn1 = 1.0f / sqrtf(1.0f + ct * ct);
        cs1 = ct * sn1;
    } else {
        if (ab == 0.0f) { cs1 = 1.0f; sn1 = 0.0f; }
        else {
            float tn = -cs / tb;
            cs1 = 1.0f / sqrtf(1.0f + tn * tn);
            sn1 = tn * cs1;
        }
    }
    if (sgn1 == sgn2) { float tn = cs1; cs1 = -sn1; sn1 = tn; }
}

__device__ void ssteqr3(float d[4], float e[3], float z[4][4]) {
    const float eps    = 5.9604645e-08f;
    const float eps2   = eps * eps;
    const float safmin = 1.17549435e-38f;
    const float safmax = 1.0f / 1.17549435e-38f;
    const float ssfmax = sqrtf(safmax) / 3.0f;
    const float ssfmin = sqrtf(safmin) / eps2;
    const int n = 3;

    for (int i = 1; i <= 3; ++i)
        for (int j = 1; j <= 3; ++j)
            z[i][j] = (i == j) ? 1.0f : 0.0f;

    int nmaxit = n * 30, jtot = 0;
    int l1 = 1;
    int l = 1, m = 1, lsv = 1, lend = 1, lendsv = 1, iscale = 0;
    float anorm = 0.0f, p, g, r, c, s, f, b, rt1, rt2;
    float wc[3], ws[3];

L10:
    if (l1 > n) goto L160;
    if (l1 > 1) e[l1 - 1] = 0.0f;
    if (l1 <= n - 1) {
        for (m = l1; m <= n - 1; ++m) {
            float tst = fabsf(e[m]);
            if (tst == 0.0f) goto L30;
            if (tst <= (sqrtf(fabsf(d[m])) * sqrtf(fabsf(d[m + 1]))) * eps) {
                e[m] = 0.0f;
                goto L30;
            }
        }
    }
    m = n;
L30:
    l = l1; lsv = l; lend = m; lendsv = lend; l1 = m + 1;
    if (lend == l) goto L10;

    anorm = 0.0f;
    for (int i = l; i <= lend; ++i)     anorm = fmaxf(anorm, fabsf(d[i]));
    for (int i = l; i <= lend - 1; ++i) anorm = fmaxf(anorm, fabsf(e[i]));
    iscale = 0;
    if (anorm == 0.0f) goto L10;
    if (anorm > ssfmax) {
        iscale = 1;
        float mul = ssfmax / anorm;
        for (int i = l; i <= lend; ++i)     d[i] *= mul;
        for (int i = l; i <= lend - 1; ++i) e[i] *= mul;
    } else if (anorm < ssfmin) {
        iscale = 2;
        float mul = ssfmin / anorm;
        for (int i = l; i <= lend; ++i)     d[i] *= mul;
        for (int i = l; i <= lend - 1; ++i) e[i] *= mul;
    }

    if (fabsf(d[lend]) < fabsf(d[l])) { lend = lsv; l = lendsv; }

    if (lend > l) {
L40:
        if (l != lend) {
            for (m = l; m <= lend - 1; ++m) {
                float tst = fabsf(e[m]); tst = tst * tst;
                if (tst <= (eps2 * fabsf(d[m])) * fabsf(d[m + 1]) + safmin) goto L60;
            }
        }
        m = lend;
L60:
        if (m < lend) e[m] = 0.0f;
        p = d[l];
        if (m == l) goto L80;
        if (m == l + 1) {
            slaev2f(d[l], e[l], d[l + 1], rt1, rt2, c, s);
            {
                float ct = c, st = s;
                if (!(ct == 1.0f && st == 0.0f)) {
                    for (int i = 1; i <= 3; ++i) {
                        float temp   = z[i][l + 1];
                        z[i][l + 1]  = ct * temp - st * z[i][l];
                        z[i][l]      = st * temp + ct * z[i][l];
                    }
                }
            }
            d[l] = rt1; d[l + 1] = rt2; e[l] = 0.0f;
            l += 2;
            if (l <= lend) goto L40;
            goto L140;
        }
        if (jtot == nmaxit) goto L140;
        ++jtot;
        g = (d[l + 1] - p) / (2.0f * e[l]);
        r = slapy2f(g, 1.0f);
        g = d[m] - p + (e[l] / (g + copysignf(r, g)));
        s = 1.0f; c = 1.0f; p = 0.0f;
        for (int i = m - 1; i >= l; --i) {
            f = s * e[i]; b = c * e[i];
            slartgf(g, f, c, s, r);
            if (i != m - 1) e[i + 1] = r;
            g = d[i + 1] - p;
            r = (d[i] - g) * s + 2.0f * c * b;
            p = s * r;
            d[i + 1] = g + p;
            g = c * r - b;
            wc[i] = c; ws[i] = -s;
        }
        {
            int mm = m - l + 1;
            for (int j = mm - 1; j >= 1; --j) {
                float ct = wc[l + j - 1], st = ws[l + j - 1];
                if (!(ct == 1.0f && st == 0.0f)) {
                    for (int i = 1; i <= 3; ++i) {
                        float temp       = z[i][l + j];
                        z[i][l + j]      = ct * temp - st * z[i][l + j - 1];
                        z[i][l + j - 1]  = st * temp + ct * z[i][l + j - 1];
                    }
                }
            }
        }
        d[l] -= p;
        e[l] = g;
        goto L40;
L80:
        d[l] = p;
        ++l;
        if (l <= lend) goto L40;
        goto L140;
    } else {
L90:
        if (l != lend) {
            for (m = l; m >= lend + 1; --m) {
                float tst = fabsf(e[m - 1]); tst = tst * tst;
                if (tst <= (eps2 * fabsf(d[m])) * fabsf(d[m - 1]) + safmin) goto L110;
            }
        }
        m = lend;
L110:
        if (m > lend) e[m - 1] = 0.0f;
        p = d[l];
        if (m == l) goto L130;
        if (m == l - 1) {
            slaev2f(d[l - 1], e[l - 1], d[l], rt1, rt2, c, s);
            {
                float ct = c, st = s;
                if (!(ct == 1.0f && st == 0.0f)) {
                    for (int i = 1; i <= 3; ++i) {
                        float temp  = z[i][l];
                        z[i][l]     = ct * temp - st * z[i][l - 1];
                        z[i][l - 1] = st * temp + ct * z[i][l - 1];
                    }
                }
            }
            d[l - 1] = rt1; d[l] = rt2; e[l - 1] = 0.0f;
            l -= 2;
            if (l >= lend) goto L90;
            goto L140;
        }
        if (jtot == nmaxit) goto L140;
        ++jtot;
        g = (d[l - 1] - p) / (2.0f * e[l - 1]);
        r = slapy2f(g, 1.0f);
        g = d[m] - p + (e[l - 1] / (g + copysignf(r, g)));
        s = 1.0f; c = 1.0f; p = 0.0f;
        for (int i = m; i <= l - 1; ++i) {
            f = s * e[i]; b = c * e[i];
            slartgf(g, f, c, s, r);
            if (i != m) e[i - 1] = r;
            g = d[i] - p;
            r = (d[i + 1] - g) * s + 2.0f * c * b;
            p = s * r;
            d[i] = g + p;
            g = c * r - b;
            wc[i] = c; ws[i] = s;
        }
        {
            int mm = l - m + 1;
            for (int j = 1; j <= mm - 1; ++j) {
                float ct = wc[m + j - 1], st = ws[m + j - 1];
                if (!(ct == 1.0f && st == 0.0f)) {
                    for (int i = 1; i <= 3; ++i) {
                        float temp       = z[i][m + j];
                        z[i][m + j]      = ct * temp - st * z[i][m + j - 1];
                        z[i][m + j - 1]  = st * temp + ct * z[i][m + j - 1];
                    }
                }
            }
        }
        d[l] -= p;
        e[l - 1] = g;
        goto L90;
L130:
        d[l] = p;
        --l;
        if (l >= lend) goto L90;
        goto L140;
    }

L140:
    if (iscale == 1) {
        float mul = anorm / ssfmax;
        for (int i = lsv; i <= lendsv; ++i)     d[i] *= mul;
        for (int i = lsv; i <= lendsv - 1; ++i) e[i] *= mul;
    } else if (iscale == 2) {
        float mul = anorm / ssfmin;
        for (int i = lsv; i <= lendsv; ++i)     d[i] *= mul;
        for (int i = lsv; i <= lendsv - 1; ++i) e[i] *= mul;
    }
    if (jtot < nmaxit) goto L10;
    goto L160;

L160:
    for (int ii = 2; ii <= n; ++ii) {
        int i = ii - 1, k = i;
        float pp = d[i];
        for (int j = ii; j <= n; ++j)
            if (d[j] < pp) { k = j; pp = d[j]; }
        if (k != i) {
            d[k] = d[i]; d[i] = pp;
            for (int rr = 1; rr <= 3; ++rr) {
                float t = z[rr][i]; z[rr][i] = z[rr][k]; z[rr][k] = t;
            }
        }
    }
}

__device__ void eigvec_smallest3(const float cov[6], float nrm[3]) {
    float a00 = cov[0], a10 = cov[1], a20 = cov[2];
    float a11 = cov[3], a21 = cov[4], a22 = cov[5];

    float tau1, beta, v2 = 0.0f;
    float xnorm = fabsf(a20);
    if (xnorm == 0.0f) {
        tau1 = 0.0f; beta = a10;
    } else {
        beta = -copysignf(slapy2f(a10, xnorm), a10);
        tau1 = (beta - a10) / beta;
        v2   = a20 / (a10 - beta);
    }
    float e0 = beta;
    if (tau1 != 0.0f) {
        float x0 = tau1 * (a11 + a21 * v2);
        float x1 = tau1 * (a21 + a22 * v2);
        float al = -0.5f * tau1 * (x0 + x1 * v2);
        x0 += al; x1 += al * v2;
        a11 = a11 - x0 - x0;
        a21 = a21 - v2 * x0 - x1;
        a22 = a22 - v2 * x1 - v2 * x1;
    }
    float d[4] = {0.0f, a00, a11, a22};
    float e[3] = {0.0f, e0, a21};
    float z[4][4];
    ssteqr3(d, e, z);

    float z1 = z[1][1], z2 = z[2][1], z3 = z[3][1];
    if (tau1 != 0.0f) {
        float w = z2 + v2 * z3;
        z2 -= tau1 * w;
        z3 -= tau1 * w * v2;
    }
    nrm[0] = z1; nrm[1] = z2; nrm[2] = z3;
}

// ======= K1: fused chamfer + count, split over SEG j-segments ==========
__global__ void __launch_bounds__(TPB) scan_kernel(
    const float* __restrict__ pred, const float* __restrict__ gt) {
    const int side = blockIdx.z / SEG;
    const int seg  = blockIdx.z % SEG;
    const int b = blockIdx.y;
    const int i = blockIdx.x * TPB + threadIdx.x;
    const float* P = (side ? gt : pred) + (size_t)b * NPTS * 3;
    const float* Q = (side ? pred : gt) + (size_t)b * NPTS * 3;

    const float px = P[i * 3 + 0], py = P[i * 3 + 1], pz = P[i * 3 + 2];
    const float pn = norm2f(px, py, pz);

    __shared__ float4 s[TILE];
    const int j0 = seg * SEGLEN;

    // ---- chamfer partial over Q[j0, j0+SEGLEN) ----
    float cm[4];
#pragma unroll
    for (int u = 0; u < 4; ++u) cm[u] = __int_as_float(0x7f800000);
    for (int tile = 0; tile < SEGLEN; tile += TILE) {
        __syncthreads();
        {
            int j = j0 + tile + threadIdx.x;
            float qx = Q[j * 3 + 0], qy = Q[j * 3 + 1], qz = Q[j * 3 + 2];
            s[threadIdx.x] = make_float4(qx, qy, qz, norm2f(qx, qy, qz));
        }
        __syncthreads();
#pragma unroll 4
        for (int t0 = 0; t0 < TILE; t0 += 4) {
#pragma unroll
            for (int u = 0; u < 4; ++u)
                cm[u] = fminf(cm[u], dist2f(px, py, pz, pn, s[t0 + u]));
        }
    }
    float cmin = fminf(fminf(cm[0], cm[1]), fminf(cm[2], cm[3]));

    // ---- exact counts at NTH thresholds over P[j0, j0+SEGLEN) ----
    int c[NTH];
#pragma unroll
    for (int k = 0; k < NTH; ++k) c[k] = 0;
    for (int tile = 0; tile < SEGLEN; tile += TILE) {
        __syncthreads();
        {
            int j = j0 + tile + threadIdx.x;
            float qx = P[j * 3 + 0], qy = P[j * 3 + 1], qz = P[j * 3 + 2];
            s[threadIdx.x] = make_float4(qx, qy, qz, norm2f(qx, qy, qz));
        }
        __syncthreads();
#pragma unroll 4
        for (int t = 0; t < TILE; ++t) {
            float d2 = dist2f(px, py, pz, pn, s[t]);
#pragma unroll
            for (int k = 0; k < NTH; ++k)
                c[k] += (d2 < thval(k)) ? 1 : 0;
        }
    }

    const size_t base = ((size_t)(side * BATCH + b) * NPTS + i) * SEG + seg;
    g_cdp[base] = cmin;
    g_cntp[base] = make_uint4((unsigned)c[0] | ((unsigned)c[1] << 16),
                              (unsigned)c[2] | ((unsigned)c[3] << 16),
                              (unsigned)c[4] | ((unsigned)c[5] << 16), 0u);
}

// ====== K2: combine segment partials -> chamfer min + threshold T* =====
__global__ void __launch_bounds__(256) combine_kernel() {
    const int idx = blockIdx.x * 256 + threadIdx.x;   // 0 .. 2*B*N-1
    const size_t base = (size_t)idx * SEG;
    float cmin = __int_as_float(0x7f800000);
    int c[NTH];
#pragma unroll
    for (int k = 0; k < NTH; ++k) c[k] = 0;
#pragma unroll
    for (int sg = 0; sg < SEG; ++sg) {
        cmin = fminf(cmin, g_cdp[base + sg]);
        uint4 u = g_cntp[base + sg];
        c[0] += (int)(u.x & 0xffffu); c[1] += (int)(u.x >> 16);
        c[2] += (int)(u.y & 0xffffu); c[3] += (int)(u.y >> 16);
        c[4] += (int)(u.z & 0xffffu); c[5] += (int)(u.z >> 16);
    }
    float tsel = -1.0f;
#pragma unroll
    for (int k = NTH - 1; k >= 0; --k)
        if (c[k] >= KN) tsel = (c[k] <= CAP) ? thval(k) : -1.0f;
    g_thresh[idx] = tsel;
    if (idx < BATCH * NPTS) g_cd0[idx] = cmin;
    else                    g_cd1[idx - BATCH * NPTS] = cmin;
}

// ====== K3: predicated collect into smem buffer + stable select ========
__device__ __forceinline__ void insert16(float (&key)[KN], int (&kid)[KN],
                                          float cd, int ci) {
    bool carry = true;
#pragma unroll
    for (int k = KN - 1; k > 0; --k) {
        bool mv = carry && (cd < key[k - 1]);
        float nk = mv ? key[k - 1] : cd;
        int   ni = mv ? kid[k - 1] : ci;
        if (carry) { key[k] = nk; kid[k] = ni; }
        carry = mv;
    }
    if (carry) { key[0] = cd; kid[0] = ci; }
}

// dynamic smem: float4 tile[TILE] | float d2buf[CAP][TPB] | u16 idxbuf[CAP][TPB]
#define K3_SMEM (TILE * 16 + CAP * TPB * 4 + CAP * TPB * 2)

__global__ void __launch_bounds__(TPB) select_kernel(
    const float* __restrict__ pred, const float* __restrict__ gt) {
    extern __shared__ char sm[];
    float4* s = (float4*)sm;
    float* d2buf = (float*)(sm + TILE * 16);
    unsigned short* idxbuf = (unsigned short*)(sm + TILE * 16 + CAP * TPB * 4);

    const int side = blockIdx.z;
    const int b = blockIdx.y;
    const int tid = threadIdx.x;
    const int i = blockIdx.x * TPB + tid;
    const float* P = (side ? gt : pred) + (size_t)b * NPTS * 3;

    const float px = P[i * 3 + 0], py = P[i * 3 + 1], pz = P[i * 3 + 2];
    const float pn = norm2f(px, py, pz);
    const float T = g_thresh[(size_t)(side * BATCH + b) * NPTS + i];

    // ---- collect pass: predicated append ----
    int cnt = 0;
    for (int tile = 0; tile < NPTS; tile += TILE) {
        __syncthreads();
        {
            int j = tile + threadIdx.x;
            float qx = P[j * 3 + 0], qy = P[j * 3 + 1], qz = P[j * 3 + 2];
            s[threadIdx.x] = make_float4(qx, qy, qz, norm2f(qx, qy, qz));
        }
        __syncthreads();
#pragma unroll 4
        for (int t = 0; t < TILE; ++t) {
            float d2 = dist2f(px, py, pz, pn, s[t]);
            bool take = (d2 < T) && (cnt < CAP);   // T = -1 -> never
            if (take) {
                d2buf[cnt * TPB + tid] = d2;
                idxbuf[cnt * TPB + tid] = (unsigned short)(tile + t);
                ++cnt;
            }
        }
    }

    float key[KN]; int kid[KN];
    bool fb = (cnt < KN);
    int anyfb = __syncthreads_or(fb ? 1 : 0);

    if (anyfb) {
        // block-uniform exact fallback
#pragma unroll
        for (int k = 0; k < KN; ++k) { key[k] = __int_as_float(0x7f800000); kid[k] = 0; }
        for (int tile = 0; tile < NPTS; tile += TILE) {
            __syncthreads();
            {
                int j = tile + threadIdx.x;
                float qx = P[j * 3 + 0], qy = P[j * 3 + 1], qz = P[j * 3 + 2];
                s[threadIdx.x] = make_float4(qx, qy, qz, norm2f(qx, qy, qz));
            }
            __syncthreads();
            for (int t = 0; t < TILE; ++t) {
                float d2 = dist2f(px, py, pz, pn, s[t]);
                if (d2 < key[KN - 1]) insert16(key, kid, d2, tile + t);
            }
        }
    } else {
        // stable strict-min extraction (lowest index wins ties == top_k order)
#pragma unroll
        for (int r = 0; r < KN; ++r) {
            float best = __int_as_float(0x7f800000);
            int bslot = 0;
            for (int j = 0; j < cnt; ++j) {
                float v = d2buf[j * TPB + tid];
                if (v < best) { best = v; bslot = j; }
            }
            key[r] = best;
            kid[r] = (int)idxbuf[bslot * TPB + tid];
            d2buf[bslot * TPB + tid] = __int_as_float(0x7f800000);
        }
    }

    // ---- repulsion from entries 1..4 (entry 0 = self) ----
    float rep = 0.0f;
#pragma unroll
    for (int k = 1; k <= 4; ++k) {
        float dd = sqrtf(fmaxf(key[k], 1e-12f));
        rep += fmaxf(0.02f - dd, 0.0f);
    }
    if (side == 0) g_rep[b * NPTS + i] = rep;

    int* knn = g_knn + ((size_t)(side * BATCH + b) * NPTS + i) * KN;
#pragma unroll
    for (int k = 0; k < KN; ++k) knn[k] = kid[k];
}

// ===================== K4: normals (PCA eigh) ==========================
__global__ void __launch_bounds__(TPB) normals_kernel(
    const float* __restrict__ pred, const float* __restrict__ gt) {
    const int side = blockIdx.z;
    const int b = blockIdx.y;
    const int i = blockIdx.x * TPB + threadIdx.x;
    const float* P = (side ? gt : pred) + (size_t)b * NPTS * 3;
    const int* knn = g_knn + ((size_t)(side * BATCH + b) * NPTS + i) * KN;

    float nbx[KN], nby[KN], nbz[KN];
#pragma unroll
    for (int k = 0; k < KN; ++k) {
        int j = knn[k];
        nbx[k] = P[j * 3 + 0]; nby[k] = P[j * 3 + 1]; nbz[k] = P[j * 3 + 2];
    }
    float mx = 0.0f, my = 0.0f, mz = 0.0f;
#pragma unroll
    for (int k = 0; k < KN; ++k) { mx += nbx[k]; my += nby[k]; mz += nbz[k]; }
    mx *= (1.0f / KN); my *= (1.0f / KN); mz *= (1.0f / KN);
    float cxx = 0, cxy = 0, cxz = 0, cyy = 0, cyz = 0, czz = 0;
#pragma unroll
    for (int k = 0; k < KN; ++k) {
        float dx = nbx[k] - mx, dy = nby[k] - my, dz = nbz[k] - mz;
        cxx += dx * dx; cxy += dx * dy; cxz += dx * dz;
        cyy += dy * dy; cyz += dy * dz; czz += dz * dz;
    }
    const float invK = 1.0f / KN;
    float cov[6] = {cxx * invK, cxy * invK, cxz * invK,
                    cyy * invK, cyz * invK, czz * invK};
    float nrm[3];
    eigvec_smallest3(cov, nrm);

    float* dst = (side == 0 ? g_nrm0 : g_nrm1) + (size_t)(b * NPTS + i) * 3;
    dst[0] = nrm[0]; dst[1] = nrm[1]; dst[2] = nrm[2];
}

// ---- deterministic two-stage reduction ----
__global__ void __launch_bounds__(RED_TPB) reduce_stage1_kernel() {
    __shared__ double sh0[RED_TPB], sh1[RED_TPB], sh2[RED_TPB], sh3[RED_TPB];
    const int tid = threadIdx.x;
    const int blk = blockIdx.x;
    const int per_blk = (BATCH * NPTS) / RED_BLKS;
    const int base = blk * per_blk;
    double c0 = 0.0, c1 = 0.0, rp = 0.0, dt = 0.0;
    for (int off = tid; off < per_blk; off += RED_TPB) {
        int idx = base + off;
        c0 += (double)g_cd0[idx];
        c1 += (double)g_cd1[idx];
        rp += (double)g_rep[idx];
        float dd = g_nrm0[idx * 3 + 0] * g_nrm1[idx * 3 + 0]
                 + g_nrm0[idx * 3 + 1] * g_nrm1[idx * 3 + 1]
                 + g_nrm0[idx * 3 + 2] * g_nrm1[idx * 3 + 2];
        dt += (double)dd;
    }
    sh0[tid] = c0; sh1[tid] = c1; sh2[tid] = rp; sh3[tid] = dt;
    __syncthreads();
    for (int off = RED_TPB / 2; off > 0; off >>= 1) {
        if (tid < off) {
            sh0[tid] += sh0[tid + off];
            sh1[tid] += sh1[tid + off];
            sh2[tid] += sh2[tid + off];
            sh3[tid] += sh3[tid + off];
        }
        __syncthreads();
    }
    if (tid == 0) {
        g_part[blk][0] = sh0[0];
        g_part[blk][1] = sh1[0];
        g_part[blk][2] = sh2[0];
        g_part[blk][3] = sh3[0];
    }
}

__global__ void __launch_bounds__(RED_BLKS) reduce_stage2_kernel(float* __restrict__ out) {
    __shared__ double sh0[RED_BLKS], sh1[RED_BLKS], sh2[RED_BLKS], sh3[RED_BLKS];
    const int tid = threadIdx.x;
    sh0[tid] = g_part[tid][0];
    sh1[tid] = g_part[tid][1];
    sh2[tid] = g_part[tid][2];
    sh3[tid] = g_part[tid][3];
    __syncthreads();
    for (int off = RED_BLKS / 2; off > 0; off >>= 1) {
        if (tid < off) {
            sh0[tid] += sh0[tid + off];
            sh1[tid] += sh1[tid + off];
            sh2[tid] += sh2[tid + off];
            sh3[tid] += sh3[tid + off];
        }
        __syncthreads();
    }
    if (tid == 0) {
        const double inv = 1.0 / (double)(BATCH * NPTS);
        double cd    = (sh0[0] + sh1[0]) * inv;
        double rep   = sh2[0] / ((double)BATCH * NPTS * 4.0);
        double normc = 1.0 - sh3[0] * inv;
        out[0] = (float)(cd + 0.1 * rep + 0.01 * normc);
    }
}

extern "C" void kernel_launch(void* const* d_in, const int* in_sizes, int n_in,
                              void* d_out, int out_size) {
    const float* pred = (const float*)d_in[0];
    const float* gt   = (const float*)d_in[1];
    cudaFuncSetAttribute(select_kernel,
                         cudaFuncAttributeMaxDynamicSharedMemorySize, K3_SMEM);
    dim3 grid_scan(NPTS / TPB, BATCH, 2 * SEG);
    scan_kernel<<<grid_scan, TPB>>>(pred, gt);
    combine_kernel<<<(2 * BATCH * NPTS) / 256, 256>>>();
    dim3 grid_sel(NPTS / TPB, BATCH, 2);
    select_kernel<<<grid_sel, TPB, K3_SMEM>>>(pred, gt);
    normals_kernel<<<grid_sel, TPB>>>(pred, gt);
    reduce_stage1_kernel<<<RED_BLKS, RED_TPB>>>();
    reduce_stage2_kernel<<<1, RED_BLKS>>>((float*)d_out);
}

// round 9
// speedup vs baseline: 23.5847x; 1.3886x over previous
#include <cuda_runtime.h>
#include <cuda_bf16.h>
#include <math.h>

#define BATCH 8
#define NPTS  2048
#define KN    16
#define TPB   128
#define TILE  128
#define CAP   96
#define NTH   4
#define SEG   4
#define SEGLEN (NPTS / SEG)
#define NPTS2 (2 * BATCH * NPTS)
#define RED_BLKS 32
#define RED_TPB  256

// ---------------- scratch (no allocations allowed) ----------------
__device__ float g_cd0[BATCH * NPTS];
__device__ float g_cd1[BATCH * NPTS];
__device__ float g_rep[BATCH * NPTS];
__device__ float g_nrm0[BATCH * NPTS * 3];
__device__ float g_nrm1[BATCH * NPTS * 3];
__device__ int   g_knn[NPTS2 * KN];
__device__ float g_cdp[NPTS2 * SEG];            // chamfer partial mins
__device__ uint2 g_cntp[NPTS2 * SEG];           // per-seg counts (u16 x4)
__device__ unsigned int g_koff[NPTS2];          // k* | seg offsets packed
__device__ int   g_cnt[NPTS2];                  // total candidates (-1 = fallback)
__device__ float g_cd2buf[CAP * NPTS2];         // candidate d2, [slot][point]
__device__ unsigned short g_cidx[CAP * NPTS2];  // candidate idx, [slot][point]
__device__ double g_part[RED_BLKS][4];

// pinned arithmetic shared by count & collect (must match exactly)
__device__ __forceinline__ float norm2f(float x, float y, float z) {
    return __fmaf_rn(x, x, __fmaf_rn(y, y, __fmul_rn(z, z)));
}
__device__ __forceinline__ float dist2f(float px, float py, float pz, float pn,
                                        float4 q) {
    float dot = __fmaf_rn(px, q.x, __fmaf_rn(py, q.y, __fmul_rn(pz, q.z)));
    return __fmaf_rn(-2.0f, dot, __fadd_rn(pn, q.w));
}
__device__ __forceinline__ float thval(int k) { return 0.012f * (float)(1 << k); }

// =================== LAPACK single-precision ports =====================
// Faithful ports of the routines jax/XLA-CPU hits for jnp.linalg.eigh on a
// 3x3 f32 symmetric matrix (sign conventions must match the reference).

__device__ __forceinline__ float slapy2f(float x, float y) {
    float xa = fabsf(x), ya = fabsf(y);
    float w = fmaxf(xa, ya);
    float z = fminf(xa, ya);
    if (z == 0.0f) return w;
    float q = z / w;
    return w * sqrtf(1.0f + q * q);
}

__device__ __forceinline__ void slartgf(float f, float g, float& c, float& s, float& r) {
    const float safmin = 1.17549435e-38f;
    const float safmax = 1.0f / 1.17549435e-38f;
    const float rtmin  = 1.0842021725e-19f;
    const float rtmax  = 6.5219432e+18f;
    float f1 = fabsf(f), g1 = fabsf(g);
    if (g == 0.0f) {
        c = 1.0f; s = 0.0f; r = f;
    } else if (f == 0.0f) {
        c = 0.0f; s = copysignf(1.0f, g); r = g1;
    } else {
        float d;
        if (f1 > rtmin && f1 < rtmax && g1 > rtmin && g1 < rtmax) {
            d = sqrtf(f * f + g * g);
            c = f1 / d;
            r = copysignf(d, f);
        } else {
            float u  = fminf(safmax, fmaxf(safmin, fmaxf(f1, g1)));
            float fs = f / u, gs = g / u;
            d = sqrtf(fs * fs + gs * gs);
            c = fabsf(fs) / d;
            r = copysignf(d, f) * u;
        }
        s = g / r;
    }
}

__device__ void slaev2f(float a, float b, float cc,
                        float& rt1, float& rt2, float& cs1, float& sn1) {
    float sm  = a + cc;
    float df  = a - cc;
    float adf = fabsf(df);
    float tb  = b + b;
    float ab  = fabsf(tb);
    float acmx, acmn;
    if (fabsf(a) > fabsf(cc)) { acmx = a;  acmn = cc; }
    else                      { acmx = cc; acmn = a;  }
    float rt;
    if (adf > ab)      { float q = ab / adf; rt = adf * sqrtf(1.0f + q * q); }
    else if (adf < ab) { float q = adf / ab; rt = ab  * sqrtf(1.0f + q * q); }
    else               { rt = ab * sqrtf(2.0f); }
    int sgn1;
    if (sm < 0.0f) {
        rt1 = 0.5f * (sm - rt); sgn1 = -1;
        rt2 = (acmx / rt1) * acmn - (b / rt1) * b;
    } else if (sm > 0.0f) {
        rt1 = 0.5f * (sm + rt); sgn1 = 1;
        rt2 = (acmx / rt1) * acmn - (b / rt1) * b;
    } else {
        rt1 = 0.5f * rt; rt2 = -0.5f * rt; sgn1 = 1;
    }
    int sgn2;
    float cs;
    if (df >= 0.0f) { cs = df + rt; sgn2 = 1; }
    else            { cs = df - rt; sgn2 = -1; }
    float acs = fabsf(cs);
    if (acs > ab) {
        float ct = -tb / cs;
        sn1 = 1.0f / sqrtf(1.0f + ct * ct);
        cs1 = ct * sn1;
    } else {
        if (ab == 0.0f) { cs1 = 1.0f; sn1 = 0.0f; }
        else {
            float tn = -cs / tb;
            cs1 = 1.0f / sqrtf(1.0f + tn * tn);
            sn1 = tn * cs1;
        }
    }
    if (sgn1 == sgn2) { float tn = cs1; cs1 = -sn1; sn1 = tn; }
}

__device__ void ssteqr3(float d[4], float e[3], float z[4][4]) {
    const float eps    = 5.9604645e-08f;
    const float eps2   = eps * eps;
    const float safmin = 1.17549435e-38f;
    const float safmax = 1.0f / 1.17549435e-38f;
    const float ssfmax = sqrtf(safmax) / 3.0f;
    const float ssfmin = sqrtf(safmin) / eps2;
    const int n = 3;

    for (int i = 1; i <= 3; ++i)
        for (int j = 1; j <= 3; ++j)
            z[i][j] = (i == j) ? 1.0f : 0.0f;

    int nmaxit = n * 30, jtot = 0;
    int l1 = 1;
    int l = 1, m = 1, lsv = 1, lend = 1, lendsv = 1, iscale = 0;
    float anorm = 0.0f, p, g, r, c, s, f, b, rt1, rt2;
    float wc[3], ws[3];

L10:
    if (l1 > n) goto L160;
    if (l1 > 1) e[l1 - 1] = 0.0f;
    if (l1 <= n - 1) {
        for (m = l1; m <= n - 1; ++m) {
            float tst = fabsf(e[m]);
            if (tst == 0.0f) goto L30;
            if (tst <= (sqrtf(fabsf(d[m])) * sqrtf(fabsf(d[m + 1]))) * eps) {
                e[m] = 0.0f;
                goto L30;
            }
        }
    }
    m = n;
L30:
    l = l1; lsv = l; lend = m; lendsv = lend; l1 = m + 1;
    if (lend == l) goto L10;

    anorm = 0.0f;
    for (int i = l; i <= lend; ++i)     anorm = fmaxf(anorm, fabsf(d[i]));
    for (int i = l; i <= lend - 1; ++i) anorm = fmaxf(anorm, fabsf(e[i]));
    iscale = 0;
    if (anorm == 0.0f) goto L10;
    if (anorm > ssfmax) {
        iscale = 1;
        float mul = ssfmax / anorm;
        for (int i = l; i <= lend; ++i)     d[i] *= mul;
        for (int i = l; i <= lend - 1; ++i) e[i] *= mul;
    } else if (anorm < ssfmin) {
        iscale = 2;
        float mul = ssfmin / anorm;
        for (int i = l; i <= lend; ++i)     d[i] *= mul;
        for (int i = l; i <= lend - 1; ++i) e[i] *= mul;
    }

    if (fabsf(d[lend]) < fabsf(d[l])) { lend = lsv; l = lendsv; }

    if (lend > l) {
L40:
        if (l != lend) {
            for (m = l; m <= lend - 1; ++m) {
                float tst = fabsf(e[m]); tst = tst * tst;
                if (tst <= (eps2 * fabsf(d[m])) * fabsf(d[m + 1]) + safmin) goto L60;
            }
        }
        m = lend;
L60:
        if (m < lend) e[m] = 0.0f;
        p = d[l];
        if (m == l) goto L80;
        if (m == l + 1) {
            slaev2f(d[l], e[l], d[l + 1], rt1, rt2, c, s);
            {
                float ct = c, st = s;
                if (!(ct == 1.0f && st == 0.0f)) {
                    for (int i = 1; i <= 3; ++i) {
                        float temp   = z[i][l + 1];
                        z[i][l + 1]  = ct * temp - st * z[i][l];
                        z[i][l]      = st * temp + ct * z[i][l];
                    }
                }
            }
            d[l] = rt1; d[l + 1] = rt2; e[l] = 0.0f;
            l += 2;
            if (l <= lend) goto L40;
            goto L140;
        }
        if (jtot == nmaxit) goto L140;
        ++jtot;
        g = (d[l + 1] - p) / (2.0f * e[l]);
        r = slapy2f(g, 1.0f);
        g = d[m] - p + (e[l] / (g + copysignf(r, g)));
        s = 1.0f; c = 1.0f; p = 0.0f;
        for (int i = m - 1; i >= l; --i) {
            f = s * e[i]; b = c * e[i];
            slartgf(g, f, c, s, r);
            if (i != m - 1) e[i + 1] = r;
            g = d[i + 1] - p;
            r = (d[i] - g) * s + 2.0f * c * b;
            p = s * r;
            d[i + 1] = g + p;
            g = c * r - b;
            wc[i] = c; ws[i] = -s;
        }
        {
            int mm = m - l + 1;
            for (int j = mm - 1; j >= 1; --j) {
                float ct = wc[l + j - 1], st = ws[l + j - 1];
                if (!(ct == 1.0f && st == 0.0f)) {
                    for (int i = 1; i <= 3; ++i) {
                        float temp       = z[i][l + j];
                        z[i][l + j]      = ct * temp - st * z[i][l + j - 1];
                        z[i][l + j - 1]  = st * temp + ct * z[i][l + j - 1];
                    }
                }
            }
        }
        d[l] -= p;
        e[l] = g;
        goto L40;
L80:
        d[l] = p;
        ++l;
        if (l <= lend) goto L40;
        goto L140;
    } else {
L90:
        if (l != lend) {
            for (m = l; m >= lend + 1; --m) {
                float tst = fabsf(e[m - 1]); tst = tst * tst;
                if (tst <= (eps2 * fabsf(d[m])) * fabsf(d[m - 1]) + safmin) goto L110;
            }
        }
        m = lend;
L110:
        if (m > lend) e[m - 1] = 0.0f;
        p = d[l];
        if (m == l) goto L130;
        if (m == l - 1) {
            slaev2f(d[l - 1], e[l - 1], d[l], rt1, rt2, c, s);
            {
                float ct = c, st = s;
                if (!(ct == 1.0f && st == 0.0f)) {
                    for (int i = 1; i <= 3; ++i) {
                        float temp  = z[i][l];
                        z[i][l]     = ct * temp - st * z[i][l - 1];
                        z[i][l - 1] = st * temp + ct * z[i][l - 1];
                    }
                }
            }
            d[l - 1] = rt1; d[l] = rt2; e[l - 1] = 0.0f;
            l -= 2;
            if (l >= lend) goto L90;
            goto L140;
        }
        if (jtot == nmaxit) goto L140;
        ++jtot;
        g = (d[l - 1] - p) / (2.0f * e[l - 1]);
        r = slapy2f(g, 1.0f);
        g = d[m] - p + (e[l - 1] / (g + copysignf(r, g)));
        s = 1.0f; c = 1.0f; p = 0.0f;
        for (int i = m; i <= l - 1; ++i) {
            f = s * e[i]; b = c * e[i];
            slartgf(g, f, c, s, r);
            if (i != m) e[i - 1] = r;
            g = d[i] - p;
            r = (d[i + 1] - g) * s + 2.0f * c * b;
            p = s * r;
            d[i] = g + p;
            g = c * r - b;
            wc[i] = c; ws[i] = s;
        }
        {
            int mm = l - m + 1;
            for (int j = 1; j <= mm - 1; ++j) {
                float ct = wc[m + j - 1], st = ws[m + j - 1];
                if (!(ct == 1.0f && st == 0.0f)) {
                    for (int i = 1; i <= 3; ++i) {
                        float temp       = z[i][m + j];
                        z[i][m + j]      = ct * temp - st * z[i][m + j - 1];
                        z[i][m + j - 1]  = st * temp + ct * z[i][m + j - 1];
                    }
                }
            }
        }
        d[l] -= p;
        e[l - 1] = g;
        goto L90;
L130:
        d[l] = p;
        --l;
        if (l >= lend) goto L90;
        goto L140;
    }

L140:
    if (iscale == 1) {
        float mul = anorm / ssfmax;
        for (int i = lsv; i <= lendsv; ++i)     d[i] *= mul;
        for (int i = lsv; i <= lendsv - 1; ++i) e[i] *= mul;
    } else if (iscale == 2) {
        float mul = anorm / ssfmin;
        for (int i = lsv; i <= lendsv; ++i)     d[i] *= mul;
        for (int i = lsv; i <= lendsv - 1; ++i) e[i] *= mul;
    }
    if (jtot < nmaxit) goto L10;
    goto L160;

L160:
    for (int ii = 2; ii <= n; ++ii) {
        int i = ii - 1, k = i;
        float pp = d[i];
        for (int j = ii; j <= n; ++j)
            if (d[j] < pp) { k = j; pp = d[j]; }
        if (k != i) {
            d[k] = d[i]; d[i] = pp;
            for (int rr = 1; rr <= 3; ++rr) {
                float t = z[rr][i]; z[rr][i] = z[rr][k]; z[rr][k] = t;
            }
        }
    }
}

__device__ void eigvec_smallest3(const float cov[6], float nrm[3]) {
    float a00 = cov[0], a10 = cov[1], a20 = cov[2];
    float a11 = cov[3], a21 = cov[4], a22 = cov[5];

    float tau1, beta, v2 = 0.0f;
    float xnorm = fabsf(a20);
    if (xnorm == 0.0f) {
        tau1 = 0.0f; beta = a10;
    } else {
        beta = -copysignf(slapy2f(a10, xnorm), a10);
        tau1 = (beta - a10) / beta;
        v2   = a20 / (a10 - beta);
    }
    float e0 = beta;
    if (tau1 != 0.0f) {
        float x0 = tau1 * (a11 + a21 * v2);
        float x1 = tau1 * (a21 + a22 * v2);
        float al = -0.5f * tau1 * (x0 + x1 * v2);
        x0 += al; x1 += al * v2;
        a11 = a11 - x0 - x0;
        a21 = a21 - v2 * x0 - x1;
        a22 = a22 - v2 * x1 - v2 * x1;
    }
    float d[4] = {0.0f, a00, a11, a22};
    float e[3] = {0.0f, e0, a21};
    float z[4][4];
    ssteqr3(d, e, z);

    float z1 = z[1][1], z2 = z[2][1], z3 = z[3][1];
    if (tau1 != 0.0f) {
        float w = z2 + v2 * z3;
        z2 -= tau1 * w;
        z3 -= tau1 * w * v2;
    }
    nrm[0] = z1; nrm[1] = z2; nrm[2] = z3;
}

// ======= K1: fused chamfer + count, split over SEG j-segments ==========
__global__ void __launch_bounds__(TPB) scan_kernel(
    const float* __restrict__ pred, const float* __restrict__ gt) {
    const int side = blockIdx.z / SEG;
    const int seg  = blockIdx.z % SEG;
    const int b = blockIdx.y;
    const int i = blockIdx.x * TPB + threadIdx.x;
    const float* P = (side ? gt : pred) + (size_t)b * NPTS * 3;
    const float* Q = (side ? pred : gt) + (size_t)b * NPTS * 3;

    const float px = P[i * 3 + 0], py = P[i * 3 + 1], pz = P[i * 3 + 2];
    const float pn = norm2f(px, py, pz);

    __shared__ float4 s[TILE];
    const int j0 = seg * SEGLEN;

    // ---- chamfer partial over Q[j0, j0+SEGLEN) ----
    float cm[4];
#pragma unroll
    for (int u = 0; u < 4; ++u) cm[u] = __int_as_float(0x7f800000);
    for (int tile = 0; tile < SEGLEN; tile += TILE) {
        __syncthreads();
        {
            int j = j0 + tile + threadIdx.x;
            float qx = Q[j * 3 + 0], qy = Q[j * 3 + 1], qz = Q[j * 3 + 2];
            s[threadIdx.x] = make_float4(qx, qy, qz, norm2f(qx, qy, qz));
        }
        __syncthreads();
#pragma unroll 4
        for (int t0 = 0; t0 < TILE; t0 += 4) {
#pragma unroll
            for (int u = 0; u < 4; ++u)
                cm[u] = fminf(cm[u], dist2f(px, py, pz, pn, s[t0 + u]));
        }
    }
    float cmin = fminf(fminf(cm[0], cm[1]), fminf(cm[2], cm[3]));

    // ---- exact counts at NTH thresholds over P[j0, j0+SEGLEN) ----
    int c[NTH];
#pragma unroll
    for (int k = 0; k < NTH; ++k) c[k] = 0;
    for (int tile = 0; tile < SEGLEN; tile += TILE) {
        __syncthreads();
        {
            int j = j0 + tile + threadIdx.x;
            float qx = P[j * 3 + 0], qy = P[j * 3 + 1], qz = P[j * 3 + 2];
            s[threadIdx.x] = make_float4(qx, qy, qz, norm2f(qx, qy, qz));
        }
        __syncthreads();
#pragma unroll 4
        for (int t = 0; t < TILE; ++t) {
            float d2 = dist2f(px, py, pz, pn, s[t]);
#pragma unroll
            for (int k = 0; k < NTH; ++k)
                c[k] += (d2 < thval(k)) ? 1 : 0;
        }
    }

    const size_t base = ((size_t)(side * BATCH + b) * NPTS + i) * SEG + seg;
    g_cdp[base] = cmin;
    g_cntp[base] = make_uint2((unsigned)c[0] | ((unsigned)c[1] << 16),
                              (unsigned)c[2] | ((unsigned)c[3] << 16));
}

// == K2: merge seg partials -> chamfer min, k*, per-seg buffer offsets ===
__global__ void __launch_bounds__(256) combine_kernel() {
    const int idx = blockIdx.x * 256 + threadIdx.x;   // 0 .. NPTS2-1
    const size_t base = (size_t)idx * SEG;
    float cmin = __int_as_float(0x7f800000);
    uint2 cp[SEG];
#pragma unroll
    for (int sg = 0; sg < SEG; ++sg) {
        cmin = fminf(cmin, g_cdp[base + sg]);
        cp[sg] = g_cntp[base + sg];
    }
    int c[NTH];
#pragma unroll
    for (int k = 0; k < NTH; ++k) c[k] = 0;
#pragma unroll
    for (int sg = 0; sg < SEG; ++sg) {
        c[0] += (int)(cp[sg].x & 0xffffu); c[1] += (int)(cp[sg].x >> 16);
        c[2] += (int)(cp[sg].y & 0xffffu); c[3] += (int)(cp[sg].y >> 16);
    }
    int ksel = 15;
#pragma unroll
    for (int k = NTH - 1; k >= 0; --k)
        if (c[k] >= KN) ksel = (c[k] <= CAP) ? k : 15;

    unsigned koff; int cnt;
    if (ksel < NTH) {
        int per[SEG];
#pragma unroll
        for (int sg = 0; sg < SEG; ++sg) {
            unsigned w = (ksel < 2) ? cp[sg].x : cp[sg].y;
            per[sg] = (int)((ksel & 1) ? (w >> 16) : (w & 0xffffu));
        }
        int off1 = per[0];
        int off2 = off1 + per[1];
        int off3 = off2 + per[2];
        cnt = off3 + per[3];
        koff = (unsigned)ksel | ((unsigned)off1 << 4) |
               ((unsigned)off2 << 12) | ((unsigned)off3 << 20);
    } else {
        koff = 15u;
        cnt = -1;
    }
    g_koff[idx] = koff;
    g_cnt[idx]  = cnt;
    if (idx < BATCH * NPTS) g_cd0[idx] = cmin;
    else                    g_cd1[idx - BATCH * NPTS] = cmin;
}

// ===== K3: collect candidates into global buffer, split 4x over j ======
__global__ void __launch_bounds__(TPB) collect_kernel(
    const float* __restrict__ pred, const float* __restrict__ gt) {
    const int side = blockIdx.z / SEG;
    const int seg  = blockIdx.z % SEG;
    const int b = blockIdx.y;
    const int i = blockIdx.x * TPB + threadIdx.x;
    const int pidx = (side * BATCH + b) * NPTS + i;
    const float* P = (side ? gt : pred) + (size_t)b * NPTS * 3;

    const float px = P[i * 3 + 0], py = P[i * 3 + 1], pz = P[i * 3 + 2];
    const float pn = norm2f(px, py, pz);

    const unsigned koff = g_koff[pidx];
    const int k = (int)(koff & 0xFu);
    const float T = (k < NTH) ? thval(k) : -1.0f;  // k==15 (fallback) -> never take
    int slot = (seg == 0) ? 0 : (int)((koff >> (8 * seg - 4)) & 0xFFu);

    __shared__ float4 s[TILE];
    const int j0 = seg * SEGLEN;

    for (int tile = 0; tile < SEGLEN; tile += TILE) {
        __syncthreads();
        {
            int j = j0 + tile + threadIdx.x;
            float qx = P[j * 3 + 0], qy = P[j * 3 + 1], qz = P[j * 3 + 2];
            s[threadIdx.x] = make_float4(qx, qy, qz, norm2f(qx, qy, qz));
        }
        __syncthreads();
#pragma unroll 4
        for (int t = 0; t < TILE; ++t) {
            float d2 = dist2f(px, py, pz, pn, s[t]);
            bool take = (d2 < T) && (slot < CAP);   // same pinned compare as count
            if (take) {
                g_cd2buf[(size_t)slot * NPTS2 + pidx] = d2;
                g_cidx[(size_t)slot * NPTS2 + pidx] = (unsigned short)(j0 + tile + t);
                ++slot;
            }
        }
    }
}

// ====== K4: stable top-16 extraction (smem), block-uniform fallback ====
__device__ __forceinline__ void insert16(float (&key)[KN], int (&kid)[KN],
                                          float cd, int ci) {
    bool carry = true;
#pragma unroll
    for (int k = KN - 1; k > 0; --k) {
        bool mv = carry && (cd < key[k - 1]);
        float nk = mv ? key[k - 1] : cd;
        int   ni = mv ? kid[k - 1] : ci;
        if (carry) { key[k] = nk; kid[k] = ni; }
        carry = mv;
    }
    if (carry) { key[0] = cd; kid[0] = ci; }
}

// dynamic smem: float4 tile[TILE] | float d2buf[CAP][TPB] | u16 idxbuf[CAP][TPB]
#define K4_SMEM (TILE * 16 + CAP * TPB * 4 + CAP * TPB * 2)

__global__ void __launch_bounds__(TPB) extract_kernel(
    const float* __restrict__ pred, const float* __restrict__ gt) {
    extern __shared__ char sm[];
    float4* s = (float4*)sm;
    float* d2buf = (float*)(sm + TILE * 16);
    unsigned short* idxbuf = (unsigned short*)(sm + TILE * 16 + CAP * TPB * 4);

    const int side = blockIdx.z;
    const int b = blockIdx.y;
    const int tid = threadIdx.x;
    const int i = blockIdx.x * TPB + tid;
    const int pidx = (side * BATCH + b) * NPTS + i;
    const float* P = (side ? gt : pred) + (size_t)b * NPTS * 3;

    const int cnt = g_cnt[pidx];
    float key[KN]; int kid[KN];

    const int anyfb = __syncthreads_or((cnt < KN) ? 1 : 0);

    if (anyfb) {
        // block-uniform exact fallback: full insert scan
        const float px = P[i * 3 + 0], py = P[i * 3 + 1], pz = P[i * 3 + 2];
        const float pn = norm2f(px, py, pz);
#pragma unroll
        for (int k = 0; k < KN; ++k) { key[k] = __int_as_float(0x7f800000); kid[k] = 0; }
        for (int tile = 0; tile < NPTS; tile += TILE) {
            __syncthreads();
            {
                int j = tile + threadIdx.x;
                float qx = P[j * 3 + 0], qy = P[j * 3 + 1], qz = P[j * 3 + 2];
                s[threadIdx.x] = make_float4(qx, qy, qz, norm2f(qx, qy, qz));
            }
            __syncthreads();
            for (int t = 0; t < TILE; ++t) {
                float d2 = dist2f(px, py, pz, pn, s[t]);
                if (d2 < key[KN - 1]) insert16(key, kid, d2, tile + t);
            }
        }
    } else {
        // stream candidates global->smem (coalesced across the warp)
        for (int slot = 0; slot < cnt; ++slot) {
            d2buf[slot * TPB + tid]  = g_cd2buf[(size_t)slot * NPTS2 + pidx];
            idxbuf[slot * TPB + tid] = g_cidx[(size_t)slot * NPTS2 + pidx];
        }
        // stable strict-min extraction: slots are in ascending-j order, so
        // strict '<' picks lowest index on ties == jax.lax.top_k ordering.
#pragma unroll
        for (int r = 0; r < KN; ++r) {
            float best = __int_as_float(0x7f800000);
            int bslot = 0;
            for (int j = 0; j < cnt; ++j) {
                float v = d2buf[j * TPB + tid];
                if (v < best) { best = v; bslot = j; }
            }
            key[r] = best;
            kid[r] = (int)idxbuf[bslot * TPB + tid];
            d2buf[bslot * TPB + tid] = __int_as_float(0x7f800000);
        }
    }

    // ---- repulsion from entries 1..4 (entry 0 = self) ----
    float rep = 0.0f;
#pragma unroll
    for (int k = 1; k <= 4; ++k) {
        float dd = sqrtf(fmaxf(key[k], 1e-12f));
        rep += fmaxf(0.02f - dd, 0.0f);
    }
    if (side == 0) g_rep[b * NPTS + i] = rep;

    int* knn = g_knn + (size_t)pidx * KN;
#pragma unroll
    for (int k = 0; k < KN; ++k) knn[k] = kid[k];
}

// ===================== K5: normals (PCA eigh) ==========================
__global__ void __launch_bounds__(TPB) normals_kernel(
    const float* __restrict__ pred, const float* __restrict__ gt) {
    const int side = blockIdx.z;
    const int b = blockIdx.y;
    const int i = blockIdx.x * TPB + threadIdx.x;
    const float* P = (side ? gt : pred) + (size_t)b * NPTS * 3;
    const int* knn = g_knn + ((size_t)(side * BATCH + b) * NPTS + i) * KN;

    float nbx[KN], nby[KN], nbz[KN];
#pragma unroll
    for (int k = 0; k < KN; ++k) {
        int j = knn[k];
        nbx[k] = P[j * 3 + 0]; nby[k] = P[j * 3 + 1]; nbz[k] = P[j * 3 + 2];
    }
    float mx = 0.0f, my = 0.0f, mz = 0.0f;
#pragma unroll
    for (int k = 0; k < KN; ++k) { mx += nbx[k]; my += nby[k]; mz += nbz[k]; }
    mx *= (1.0f / KN); my *= (1.0f / KN); mz *= (1.0f / KN);
    float cxx = 0, cxy = 0, cxz = 0, cyy = 0, cyz = 0, czz = 0;
#pragma unroll
    for (int k = 0; k < KN; ++k) {
        float dx = nbx[k] - mx, dy = nby[k] - my, dz = nbz[k] - mz;
        cxx += dx * dx; cxy += dx * dy; cxz += dx * dz;
        cyy += dy * dy; cyz += dy * dz; czz += dz * dz;
    }
    const float invK = 1.0f / KN;
    float cov[6] = {cxx * invK, cxy * invK, cxz * invK,
                    cyy * invK, cyz * invK, czz * invK};
    float nrm[3];
    eigvec_smallest3(cov, nrm);

    float* dst = (side == 0 ? g_nrm0 : g_nrm1) + (size_t)(b * NPTS + i) * 3;
    dst[0] = nrm[0]; dst[1] = nrm[1]; dst[2] = nrm[2];
}

// ---- deterministic two-stage reduction ----
__global__ void __launch_bounds__(RED_TPB) reduce_stage1_kernel() {
    __shared__ double sh0[RED_TPB], sh1[RED_TPB], sh2[RED_TPB], sh3[RED_TPB];
    const int tid = threadIdx.x;
    const int blk = blockIdx.x;
    const int per_blk = (BATCH * NPTS) / RED_BLKS;
    const int base = blk * per_blk;
    double c0 = 0.0, c1 = 0.0, rp = 0.0, dt = 0.0;
    for (int off = tid; off < per_blk; off += RED_TPB) {
        int idx = base + off;
        c0 += (double)g_cd0[idx];
        c1 += (double)g_cd1[idx];
        rp += (double)g_rep[idx];
        float dd = g_nrm0[idx * 3 + 0] * g_nrm1[idx * 3 + 0]
                 + g_nrm0[idx * 3 + 1] * g_nrm1[idx * 3 + 1]
                 + g_nrm0[idx * 3 + 2] * g_nrm1[idx * 3 + 2];
        dt += (double)dd;
    }
    sh0[tid] = c0; sh1[tid] = c1; sh2[tid] = rp; sh3[tid] = dt;
    __syncthreads();
    for (int off = RED_TPB / 2; off > 0; off >>= 1) {
        if (tid < off) {
            sh0[tid] += sh0[tid + off];
            sh1[tid] += sh1[tid + off];
            sh2[tid] += sh2[tid + off];
            sh3[tid] += sh3[tid + off];
        }
        __syncthreads();
    }
    if (tid == 0) {
        g_part[blk][0] = sh0[0];
        g_part[blk][1] = sh1[0];
        g_part[blk][2] = sh2[0];
        g_part[blk][3] = sh3[0];
    }
}

__global__ void __launch_bounds__(RED_BLKS) reduce_stage2_kernel(float* __restrict__ out) {
    __shared__ double sh0[RED_BLKS], sh1[RED_BLKS], sh2[RED_BLKS], sh3[RED_BLKS];
    const int tid = threadIdx.x;
    sh0[tid] = g_part[tid][0];
    sh1[tid] = g_part[tid][1];
    sh2[tid] = g_part[tid][2];
    sh3[tid] = g_part[tid][3];
    __syncthreads();
    for (int off = RED_BLKS / 2; off > 0; off >>= 1) {
        if (tid < off) {
            sh0[tid] += sh0[tid + off];
            sh1[tid] += sh1[tid + off];
            sh2[tid] += sh2[tid + off];
            sh3[tid] += sh3[tid + off];
        }
        __syncthreads();
    }
    if (tid == 0) {
        const double inv = 1.0 / (double)(BATCH * NPTS);
        double cd    = (sh0[0] + sh1[0]) * inv;
        double rep   = sh2[0] / ((double)BATCH * NPTS * 4.0);
        double normc = 1.0 - sh3[0] * inv;
        out[0] = (float)(cd + 0.1 * rep + 0.01 * normc);
    }
}

extern "C" void kernel_launch(void* const* d_in, const int* in_sizes, int n_in,
                              void* d_out, int out_size) {
    const float* pred = (const float*)d_in[0];
    const float* gt   = (const float*)d_in[1];
    cudaFuncSetAttribute(extract_kernel,
                         cudaFuncAttributeMaxDynamicSharedMemorySize, K4_SMEM);
    dim3 grid_seg(NPTS / TPB, BATCH, 2 * SEG);
    dim3 grid_pt(NPTS / TPB, BATCH, 2);
    scan_kernel<<<grid_seg, TPB>>>(pred, gt);
    combine_kernel<<<NPTS2 / 256, 256>>>();
    collect_kernel<<<grid_seg, TPB>>>(pred, gt);
    extract_kernel<<<grid_pt, TPB, K4_SMEM>>>(pred, gt);
    normals_kernel<<<grid_pt, TPB>>>(pred, gt);
    reduce_stage1_kernel<<<RED_BLKS, RED_TPB>>>();
    reduce_stage2_kernel<<<1, RED_BLKS>>>((float*)d_out);
}

// round 11
// speedup vs baseline: 27.2699x; 1.1563x over previous
#include <cuda_runtime.h>
#include <cuda_bf16.h>
#include <math.h>

#define BATCH 8
#define NPTS  2048
#define KN    16
#define TPB   128
#define TILE  128
#define CAP   96
#define NTH   4
#define SEG   4
#define SEGLEN (NPTS / SEG)
#define BN    (BATCH * NPTS)
#define NPTS2 (2 * BN)
#define RED_BLKS 32
#define RED_TPB  256

// ---------------- scratch (no allocations allowed) ----------------
__device__ float g_rep[BN];
__device__ float g_nrm0[BN * 3];
__device__ float g_nrm1[BN * 3];
__device__ uint2 g_cntp[NPTS2 * SEG];           // per-seg counts [pidx][seg] (R9 layout)
__device__ unsigned int g_koff[NPTS2];          // k* | seg offsets packed
__device__ int   g_cnt[NPTS2];                  // total candidates (-1 = fallback)
__device__ float g_cdp[NPTS2 * SEG];            // chamfer partial mins [pidx][seg]
__device__ float g_cd2buf[CAP * NPTS2];         // candidate d2 [slot][pidx]
__device__ unsigned short g_cidx[CAP * NPTS2];  // candidate idx [slot][pidx]
__device__ double g_part[RED_BLKS][4];

// pinned arithmetic shared by count & collect (must match exactly)
__device__ __forceinline__ float norm2f(float x, float y, float z) {
    return __fmaf_rn(x, x, __fmaf_rn(y, y, __fmul_rn(z, z)));
}
__device__ __forceinline__ float dist2f(float px, float py, float pz, float pn,
                                        float4 q) {
    float dot = __fmaf_rn(px, q.x, __fmaf_rn(py, q.y, __fmul_rn(pz, q.z)));
    return __fmaf_rn(-2.0f, dot, __fadd_rn(pn, q.w));
}
__device__ __forceinline__ float thval(int k) { return 0.012f * (float)(1 << k); }

// =================== LAPACK single-precision ports =====================
// Faithful ports of the routines jax/XLA-CPU hits for jnp.linalg.eigh on a
// 3x3 f32 symmetric matrix (sign conventions must match the reference).

__device__ __forceinline__ float slapy2f(float x, float y) {
    float xa = fabsf(x), ya = fabsf(y);
    float w = fmaxf(xa, ya);
    float z = fminf(xa, ya);
    if (z == 0.0f) return w;
    float q = z / w;
    return w * sqrtf(1.0f + q * q);
}

__device__ __forceinline__ void slartgf(float f, float g, float& c, float& s, float& r) {
    const float safmin = 1.17549435e-38f;
    const float safmax = 1.0f / 1.17549435e-38f;
    const float rtmin  = 1.0842021725e-19f;
    const float rtmax  = 6.5219432e+18f;
    float f1 = fabsf(f), g1 = fabsf(g);
    if (g == 0.0f) {
        c = 1.0f; s = 0.0f; r = f;
    } else if (f == 0.0f) {
        c = 0.0f; s = copysignf(1.0f, g); r = g1;
    } else {
        float d;
        if (f1 > rtmin && f1 < rtmax && g1 > rtmin && g1 < rtmax) {
            d = sqrtf(f * f + g * g);
            c = f1 / d;
            r = copysignf(d, f);
        } else {
            float u  = fminf(safmax, fmaxf(safmin, fmaxf(f1, g1)));
            float fs = f / u, gs = g / u;
            d = sqrtf(fs * fs + gs * gs);
            c = fabsf(fs) / d;
            r = copysignf(d, f) * u;
        }
        s = g / r;
    }
}

__device__ void slaev2f(float a, float b, float cc,
                        float& rt1, float& rt2, float& cs1, float& sn1) {
    float sm  = a + cc;
    float df  = a - cc;
    float adf = fabsf(df);
    float tb  = b + b;
    float ab  = fabsf(tb);
    float acmx, acmn;
    if (fabsf(a) > fabsf(cc)) { acmx = a;  acmn = cc; }
    else                      { acmx = cc; acmn = a;  }
    float rt;
    if (adf > ab)      { float q = ab / adf; rt = adf * sqrtf(1.0f + q * q); }
    else if (adf < ab) { float q = adf / ab; rt = ab  * sqrtf(1.0f + q * q); }
    else               { rt = ab * sqrtf(2.0f); }
    int sgn1;
    if (sm < 0.0f) {
        rt1 = 0.5f * (sm - rt); sgn1 = -1;
        rt2 = (acmx / rt1) * acmn - (b / rt1) * b;
    } else if (sm > 0.0f) {
        rt1 = 0.5f * (sm + rt); sgn1 = 1;
        rt2 = (acmx / rt1) * acmn - (b / rt1) * b;
    } else {
        rt1 = 0.5f * rt; rt2 = -0.5f * rt; sgn1 = 1;
    }
    int sgn2;
    float cs;
    if (df >= 0.0f) { cs = df + rt; sgn2 = 1; }
    else            { cs = df - rt; sgn2 = -1; }
    float acs = fabsf(cs);
    if (acs > ab) {
        float ct = -tb / cs;
        sn1 = 1.0f / sqrtf(1.0f + ct * ct);
        cs1 = ct * sn1;
    } else {
        if (ab == 0.0f) { cs1 = 1.0f; sn1 = 0.0f; }
        else {
            float tn = -cs / tb;
            cs1 = 1.0f / sqrtf(1.0f + tn * tn);
            sn1 = tn * cs1;
        }
    }
    if (sgn1 == sgn2) { float tn = cs1; cs1 = -sn1; sn1 = tn; }
}

__device__ void ssteqr3(float d[4], float e[3], float z[4][4]) {
    const float eps    = 5.9604645e-08f;
    const float eps2   = eps * eps;
    const float safmin = 1.17549435e-38f;
    const float safmax = 1.0f / 1.17549435e-38f;
    const float ssfmax = sqrtf(safmax) / 3.0f;
    const float ssfmin = sqrtf(safmin) / eps2;
    const int n = 3;

    for (int i = 1; i <= 3; ++i)
        for (int j = 1; j <= 3; ++j)
            z[i][j] = (i == j) ? 1.0f : 0.0f;

    int nmaxit = n * 30, jtot = 0;
    int l1 = 1;
    int l = 1, m = 1, lsv = 1, lend = 1, lendsv = 1, iscale = 0;
    float anorm = 0.0f, p, g, r, c, s, f, b, rt1, rt2;
    float wc[3], ws[3];

L10:
    if (l1 > n) goto L160;
    if (l1 > 1) e[l1 - 1] = 0.0f;
    if (l1 <= n - 1) {
        for (m = l1; m <= n - 1; ++m) {
            float tst = fabsf(e[m]);
            if (tst == 0.0f) goto L30;
            if (tst <= (sqrtf(fabsf(d[m])) * sqrtf(fabsf(d[m + 1]))) * eps) {
                e[m] = 0.0f;
                goto L30;
            }
        }
    }
    m = n;
L30:
    l = l1; lsv = l; lend = m; lendsv = lend; l1 = m + 1;
    if (lend == l) goto L10;

    anorm = 0.0f;
    for (int i = l; i <= lend; ++i)     anorm = fmaxf(anorm, fabsf(d[i]));
    for (int i = l; i <= lend - 1; ++i) anorm = fmaxf(anorm, fabsf(e[i]));
    iscale = 0;
    if (anorm == 0.0f) goto L10;
    if (anorm > ssfmax) {
        iscale = 1;
        float mul = ssfmax / anorm;
        for (int i = l; i <= lend; ++i)     d[i] *= mul;
        for (int i = l; i <= lend - 1; ++i) e[i] *= mul;
    } else if (anorm < ssfmin) {
        iscale = 2;
        float mul = ssfmin / anorm;
        for (int i = l; i <= lend; ++i)     d[i] *= mul;
        for (int i = l; i <= lend - 1; ++i) e[i] *= mul;
    }

    if (fabsf(d[lend]) < fabsf(d[l])) { lend = lsv; l = lendsv; }

    if (lend > l) {
L40:
        if (l != lend) {
            for (m = l; m <= lend - 1; ++m) {
                float tst = fabsf(e[m]); tst = tst * tst;
                if (tst <= (eps2 * fabsf(d[m])) * fabsf(d[m + 1]) + safmin) goto L60;
            }
        }
        m = lend;
L60:
        if (m < lend) e[m] = 0.0f;
        p = d[l];
        if (m == l) goto L80;
        if (m == l + 1) {
            slaev2f(d[l], e[l], d[l + 1], rt1, rt2, c, s);
            {
                float ct = c, st = s;
                if (!(ct == 1.0f && st == 0.0f)) {
                    for (int i = 1; i <= 3; ++i) {
                        float temp   = z[i][l + 1];
                        z[i][l + 1]  = ct * temp - st * z[i][l];
                        z[i][l]      = st * temp + ct * z[i][l];
                    }
                }
            }
            d[l] = rt1; d[l + 1] = rt2; e[l] = 0.0f;
            l += 2;
            if (l <= lend) goto L40;
            goto L140;
        }
        if (jtot == nmaxit) goto L140;
        ++jtot;
        g = (d[l + 1] - p) / (2.0f * e[l]);
        r = slapy2f(g, 1.0f);
        g = d[m] - p + (e[l] / (g + copysignf(r, g)));
        s = 1.0f; c = 1.0f; p = 0.0f;
        for (int i = m - 1; i >= l; --i) {
            f = s * e[i]; b = c * e[i];
            slartgf(g, f, c, s, r);
            if (i != m - 1) e[i + 1] = r;
            g = d[i + 1] - p;
            r = (d[i] - g) * s + 2.0f * c * b;
            p = s * r;
            d[i + 1] = g + p;
            g = c * r - b;
            wc[i] = c; ws[i] = -s;
        }
        {
            int mm = m - l + 1;
            for (int j = mm - 1; j >= 1; --j) {
                float ct = wc[l + j - 1], st = ws[l + j - 1];
                if (!(ct == 1.0f && st == 0.0f)) {
                    for (int i = 1; i <= 3; ++i) {
                        float temp       = z[i][l + j];
                        z[i][l + j]      = ct * temp - st * z[i][l + j - 1];
                        z[i][l + j - 1]  = st * temp + ct * z[i][l + j - 1];
                    }
                }
            }
        }
        d[l] -= p;
        e[l] = g;
        goto L40;
L80:
        d[l] = p;
        ++l;
        if (l <= lend) goto L40;
        goto L140;
    } else {
L90:
        if (l != lend) {
            for (m = l; m >= lend + 1; --m) {
                float tst = fabsf(e[m - 1]); tst = tst * tst;
                if (tst <= (eps2 * fabsf(d[m])) * fabsf(d[m - 1]) + safmin) goto L110;
            }
        }
        m = lend;
L110:
        if (m > lend) e[m - 1] = 0.0f;
        p = d[l];
        if (m == l) goto L130;
        if (m == l - 1) {
            slaev2f(d[l - 1], e[l - 1], d[l], rt1, rt2, c, s);
            {
                float ct = c, st = s;
                if (!(ct == 1.0f && st == 0.0f)) {
                    for (int i = 1; i <= 3; ++i) {
                        float temp  = z[i][l];
                        z[i][l]     = ct * temp - st * z[i][l - 1];
                        z[i][l - 1] = st * temp + ct * z[i][l - 1];
                    }
                }
            }
            d[l - 1] = rt1; d[l] = rt2; e[l - 1] = 0.0f;
            l -= 2;
            if (l >= lend) goto L90;
            goto L140;
        }
        if (jtot == nmaxit) goto L140;
        ++jtot;
        g = (d[l - 1] - p) / (2.0f * e[l - 1]);
        r = slapy2f(g, 1.0f);
        g = d[m] - p + (e[l - 1] / (g + copysignf(r, g)));
        s = 1.0f; c = 1.0f; p = 0.0f;
        for (int i = m; i <= l - 1; ++i) {
            f = s * e[i]; b = c * e[i];
            slartgf(g, f, c, s, r);
            if (i != m) e[i - 1] = r;
            g = d[i] - p;
            r = (d[i + 1] - g) * s + 2.0f * c * b;
            p = s * r;
            d[i] = g + p;
            g = c * r - b;
            wc[i] = c; ws[i] = s;
        }
        {
            int mm = l - m + 1;
            for (int j = 1; j <= mm - 1; ++j) {
                float ct = wc[m + j - 1], st = ws[m + j - 1];
                if (!(ct == 1.0f && st == 0.0f)) {
                    for (int i = 1; i <= 3; ++i) {
                        float temp       = z[i][m + j];
                        z[i][m + j]      = ct * temp - st * z[i][m + j - 1];
                        z[i][m + j - 1]  = st * temp + ct * z[i][m + j - 1];
                    }
                }
            }
        }
        d[l] -= p;
        e[l - 1] = g;
        goto L90;
L130:
        d[l] = p;
        --l;
        if (l >= lend) goto L90;
        goto L140;
    }

L140:
    if (iscale == 1) {
        float mul = anorm / ssfmax;
        for (int i = lsv; i <= lendsv; ++i)     d[i] *= mul;
        for (int i = lsv; i <= lendsv - 1; ++i) e[i] *= mul;
    } else if (iscale == 2) {
        float mul = anorm / ssfmin;
        for (int i = lsv; i <= lendsv; ++i)     d[i] *= mul;
        for (int i = lsv; i <= lendsv - 1; ++i) e[i] *= mul;
    }
    if (jtot < nmaxit) goto L10;
    goto L160;

L160:
    for (int ii = 2; ii <= n; ++ii) {
        int i = ii - 1, k = i;
        float pp = d[i];
        for (int j = ii; j <= n; ++j)
            if (d[j] < pp) { k = j; pp = d[j]; }
        if (k != i) {
            d[k] = d[i]; d[i] = pp;
            for (int rr = 1; rr <= 3; ++rr) {
                float t = z[rr][i]; z[rr][i] = z[rr][k]; z[rr][k] = t;
            }
        }
    }
}

__device__ void eigvec_smallest3(const float cov[6], float nrm[3]) {
    float a00 = cov[0], a10 = cov[1], a20 = cov[2];
    float a11 = cov[3], a21 = cov[4], a22 = cov[5];

    float tau1, beta, v2 = 0.0f;
    float xnorm = fabsf(a20);
    if (xnorm == 0.0f) {
        tau1 = 0.0f; beta = a10;
    } else {
        beta = -copysignf(slapy2f(a10, xnorm), a10);
        tau1 = (beta - a10) / beta;
        v2   = a20 / (a10 - beta);
    }
    float e0 = beta;
    if (tau1 != 0.0f) {
        float x0 = tau1 * (a11 + a21 * v2);
        float x1 = tau1 * (a21 + a22 * v2);
        float al = -0.5f * tau1 * (x0 + x1 * v2);
        x0 += al; x1 += al * v2;
        a11 = a11 - x0 - x0;
        a21 = a21 - v2 * x0 - x1;
        a22 = a22 - v2 * x1 - v2 * x1;
    }
    float d[4] = {0.0f, a00, a11, a22};
    float e[3] = {0.0f, e0, a21};
    float z[4][4];
    ssteqr3(d, e, z);

    float z1 = z[1][1], z2 = z[2][1], z3 = z[3][1];
    if (tau1 != 0.0f) {
        float w = z2 + v2 * z3;
        z2 -= tau1 * w;
        z3 -= tau1 * w * v2;
    }
    nrm[0] = z1; nrm[1] = z2; nrm[2] = z3;
}

// ======== K1: exact counts at NTH thresholds (verbatim R9 path) ========
__global__ void __launch_bounds__(TPB) count_kernel(
    const float* __restrict__ pred, const float* __restrict__ gt) {
    const int side = blockIdx.z / SEG;
    const int seg  = blockIdx.z % SEG;
    const int b = blockIdx.y;
    const int i = blockIdx.x * TPB + threadIdx.x;
    const float* P = (side ? gt : pred) + (size_t)b * NPTS * 3;

    const float px = P[i * 3 + 0], py = P[i * 3 + 1], pz = P[i * 3 + 2];
    const float pn = norm2f(px, py, pz);

    __shared__ float4 s[TILE];
    const int j0 = seg * SEGLEN;
    int c[NTH];
#pragma unroll
    for (int k = 0; k < NTH; ++k) c[k] = 0;
    for (int tile = 0; tile < SEGLEN; tile += TILE) {
        __syncthreads();
        {
            int j = j0 + tile + threadIdx.x;
            float qx = P[j * 3 + 0], qy = P[j * 3 + 1], qz = P[j * 3 + 2];
            s[threadIdx.x] = make_float4(qx, qy, qz, norm2f(qx, qy, qz));
        }
        __syncthreads();
#pragma unroll 4
        for (int t = 0; t < TILE; ++t) {
            float d2 = dist2f(px, py, pz, pn, s[t]);
#pragma unroll
            for (int k = 0; k < NTH; ++k)
                c[k] += (d2 < thval(k)) ? 1 : 0;
        }
    }
    const size_t base = ((size_t)(side * BATCH + b) * NPTS + i) * SEG + seg;
    g_cntp[base] = make_uint2((unsigned)c[0] | ((unsigned)c[1] << 16),
                              (unsigned)c[2] | ((unsigned)c[3] << 16));
}

// ====== K2: merge seg counts -> k*, per-seg buffer offsets (R9) ========
__global__ void __launch_bounds__(256) combine_kernel() {
    const int idx = blockIdx.x * 256 + threadIdx.x;   // 0 .. NPTS2-1
    const size_t base = (size_t)idx * SEG;
    uint2 cp[SEG];
#pragma unroll
    for (int sg = 0; sg < SEG; ++sg) cp[sg] = g_cntp[base + sg];
    int c[NTH];
#pragma unroll
    for (int k = 0; k < NTH; ++k) c[k] = 0;
#pragma unroll
    for (int sg = 0; sg < SEG; ++sg) {
        c[0] += (int)(cp[sg].x & 0xffffu); c[1] += (int)(cp[sg].x >> 16);
        c[2] += (int)(cp[sg].y & 0xffffu); c[3] += (int)(cp[sg].y >> 16);
    }
    int ksel = 15;
#pragma unroll
    for (int k = NTH - 1; k >= 0; --k)
        if (c[k] >= KN) ksel = (c[k] <= CAP) ? k : 15;

    unsigned koff; int cnt;
    if (ksel < NTH) {
        int per[SEG];
#pragma unroll
        for (int sg = 0; sg < SEG; ++sg) {
            unsigned w = (ksel < 2) ? cp[sg].x : cp[sg].y;
            per[sg] = (int)((ksel & 1) ? (w >> 16) : (w & 0xffffu));
        }
        int off1 = per[0];
        int off2 = off1 + per[1];
        int off3 = off2 + per[2];
        cnt = off3 + per[3];
        koff = (unsigned)ksel | ((unsigned)off1 << 4) |
               ((unsigned)off2 << 12) | ((unsigned)off3 << 20);
    } else {
        koff = 15u;
        cnt = -1;
    }
    g_koff[idx] = koff;
    g_cnt[idx]  = cnt;
}

// ========= K3: collect candidates (verbatim R9) ========================
__global__ void __launch_bounds__(TPB) collect_kernel(
    const float* __restrict__ pred, const float* __restrict__ gt) {
    const int side = blockIdx.z / SEG;
    const int seg  = blockIdx.z % SEG;
    const int b = blockIdx.y;
    const int i = blockIdx.x * TPB + threadIdx.x;
    const int pidx = (side * BATCH + b) * NPTS + i;
    const float* P = (side ? gt : pred) + (size_t)b * NPTS * 3;

    const float px = P[i * 3 + 0], py = P[i * 3 + 1], pz = P[i * 3 + 2];
    const float pn = norm2f(px, py, pz);

    const unsigned koff = g_koff[pidx];
    const int k = (int)(koff & 0xFu);
    const float T = (k < NTH) ? thval(k) : -1.0f;  // k==15 (fallback) -> never take
    int slot = (seg == 0) ? 0 : (int)((koff >> (8 * seg - 4)) & 0xFFu);

    __shared__ float4 s[TILE];
    const int j0 = seg * SEGLEN;

    for (int tile = 0; tile < SEGLEN; tile += TILE) {
        __syncthreads();
        {
            int j = j0 + tile + threadIdx.x;
            float qx = P[j * 3 + 0], qy = P[j * 3 + 1], qz = P[j * 3 + 2];
            s[threadIdx.x] = make_float4(qx, qy, qz, norm2f(qx, qy, qz));
        }
        __syncthreads();
#pragma unroll 4
        for (int t = 0; t < TILE; ++t) {
            float d2 = dist2f(px, py, pz, pn, s[t]);
            bool take = (d2 < T) && (slot < CAP);   // same pinned compare as count
            if (take) {
                g_cd2buf[(size_t)slot * NPTS2 + pidx] = d2;
                g_cidx[(size_t)slot * NPTS2 + pidx] = (unsigned short)(j0 + tile + t);
                ++slot;
            }
        }
    }
}

// === K4: heterogeneous mega: chamfer blocks + (extract+normals) blocks ==
__device__ __forceinline__ void insert16(float (&key)[KN], int (&kid)[KN],
                                          float cd, int ci) {
    bool carry = true;
#pragma unroll
    for (int k = KN - 1; k > 0; --k) {
        bool mv = carry && (cd < key[k - 1]);
        float nk = mv ? key[k - 1] : cd;
        int   ni = mv ? kid[k - 1] : ci;
        if (carry) { key[k] = nk; kid[k] = ni; }
        carry = mv;
    }
    if (carry) { key[0] = cd; kid[0] = ci; }
}

// dynamic smem: float4 tile[TILE] | float d2buf[CAP][TPB] | u16 idxbuf[CAP][TPB]
#define MEGA_SMEM (TILE * 16 + CAP * TPB * 4 + CAP * TPB * 2)

__global__ void __launch_bounds__(TPB) mega_kernel(
    const float* __restrict__ pred, const float* __restrict__ gt) {
    extern __shared__ char sm[];
    float4* s = (float4*)sm;
    const int b = blockIdx.y;
    const int tid = threadIdx.x;

    if (blockIdx.z >= 2) {
        // ------------- chamfer role (verbatim R9 scan chamfer part) -----
        const int zz = blockIdx.z - 2;
        const int side = zz / SEG;
        const int seg  = zz % SEG;
        const int i = blockIdx.x * TPB + tid;
        const float* P = (side ? gt : pred) + (size_t)b * NPTS * 3;
        const float* Q = (side ? pred : gt) + (size_t)b * NPTS * 3;

        const float px = P[i * 3 + 0], py = P[i * 3 + 1], pz = P[i * 3 + 2];
        const float pn = norm2f(px, py, pz);
        const int j0 = seg * SEGLEN;

        float cm[4];
#pragma unroll
        for (int u = 0; u < 4; ++u) cm[u] = __int_as_float(0x7f800000);
        for (int tile = 0; tile < SEGLEN; tile += TILE) {
            __syncthreads();
            {
                int j = j0 + tile + tid;
                float qx = Q[j * 3 + 0], qy = Q[j * 3 + 1], qz = Q[j * 3 + 2];
                s[tid] = make_float4(qx, qy, qz, norm2f(qx, qy, qz));
            }
            __syncthreads();
#pragma unroll 4
            for (int t0 = 0; t0 < TILE; t0 += 4) {
#pragma unroll
                for (int u = 0; u < 4; ++u)
                    cm[u] = fminf(cm[u], dist2f(px, py, pz, pn, s[t0 + u]));
            }
        }
        float cmin = fminf(fminf(cm[0], cm[1]), fminf(cm[2], cm[3]));
        g_cdp[((size_t)(side * BATCH + b) * NPTS + i) * SEG + seg] = cmin;
        return;
    }

    // ------------- extract + normals role (verbatim R9 extract) ---------
    float* d2buf = (float*)(sm + TILE * 16);
    unsigned short* idxbuf = (unsigned short*)(sm + TILE * 16 + CAP * TPB * 4);

    const int side = blockIdx.z;
    const int i = blockIdx.x * TPB + tid;
    const int pidx = (side * BATCH + b) * NPTS + i;
    const float* P = (side ? gt : pred) + (size_t)b * NPTS * 3;

    const int cnt = g_cnt[pidx];
    float key[KN]; int kid[KN];

    const int anyfb = __syncthreads_or((cnt < KN) ? 1 : 0);

    if (anyfb) {
        // block-uniform exact fallback: full insert scan
        const float px = P[i * 3 + 0], py = P[i * 3 + 1], pz = P[i * 3 + 2];
        const float pn = norm2f(px, py, pz);
#pragma unroll
        for (int k = 0; k < KN; ++k) { key[k] = __int_as_float(0x7f800000); kid[k] = 0; }
        for (int tile = 0; tile < NPTS; tile += TILE) {
            __syncthreads();
            {
                int j = tile + tid;
                float qx = P[j * 3 + 0], qy = P[j * 3 + 1], qz = P[j * 3 + 2];
                s[tid] = make_float4(qx, qy, qz, norm2f(qx, qy, qz));
            }
            __syncthreads();
            for (int t = 0; t < TILE; ++t) {
                float d2 = dist2f(px, py, pz, pn, s[t]);
                if (d2 < key[KN - 1]) insert16(key, kid, d2, tile + t);
            }
        }
    } else {
        // stream candidates global->smem (coalesced across the warp)
        for (int slot = 0; slot < cnt; ++slot) {
            d2buf[slot * TPB + tid]  = g_cd2buf[(size_t)slot * NPTS2 + pidx];
            idxbuf[slot * TPB + tid] = g_cidx[(size_t)slot * NPTS2 + pidx];
        }
        // stable strict-min extraction: slots are in ascending-j order, so
        // strict '<' picks lowest index on ties == jax.lax.top_k ordering.
#pragma unroll
        for (int r = 0; r < KN; ++r) {
            float best = __int_as_float(0x7f800000);
            int bslot = 0;
            for (int j = 0; j < cnt; ++j) {
                float v = d2buf[j * TPB + tid];
                if (v < best) { best = v; bslot = j; }
            }
            key[r] = best;
            kid[r] = (int)idxbuf[bslot * TPB + tid];
            d2buf[bslot * TPB + tid] = __int_as_float(0x7f800000);
        }
    }

    // ---- repulsion from entries 1..4 (entry 0 = self) ----
    float rep = 0.0f;
#pragma unroll
    for (int k = 1; k <= 4; ++k) {
        float dd = sqrtf(fmaxf(key[k], 1e-12f));
        rep += fmaxf(0.02f - dd, 0.0f);
    }
    if (side == 0) g_rep[b * NPTS + i] = rep;

    // ---- fused normals epilogue (verbatim R9 normals body) ----
    float nbx[KN], nby[KN], nbz[KN];
#pragma unroll
    for (int k = 0; k < KN; ++k) {
        int j = kid[k];
        nbx[k] = P[j * 3 + 0]; nby[k] = P[j * 3 + 1]; nbz[k] = P[j * 3 + 2];
    }
    float mx = 0.0f, my = 0.0f, mz = 0.0f;
#pragma unroll
    for (int k = 0; k < KN; ++k) { mx += nbx[k]; my += nby[k]; mz += nbz[k]; }
    mx *= (1.0f / KN); my *= (1.0f / KN); mz *= (1.0f / KN);
    float cxx = 0, cxy = 0, cxz = 0, cyy = 0, cyz = 0, czz = 0;
#pragma unroll
    for (int k = 0; k < KN; ++k) {
        float dx = nbx[k] - mx, dy = nby[k] - my, dz = nbz[k] - mz;
        cxx += dx * dx; cxy += dx * dy; cxz += dx * dz;
        cyy += dy * dy; cyz += dy * dz; czz += dz * dz;
    }
    const float invK = 1.0f / KN;
    float cov[6] = {cxx * invK, cxy * invK, cxz * invK,
                    cyy * invK, cyz * invK, czz * invK};
    float nrm[3];
    eigvec_smallest3(cov, nrm);

    float* dst = (side == 0 ? g_nrm0 : g_nrm1) + (size_t)(b * NPTS + i) * 3;
    dst[0] = nrm[0]; dst[1] = nrm[1]; dst[2] = nrm[2];
}

// ---- deterministic two-stage reduction ----
__global__ void __launch_bounds__(RED_TPB) reduce_stage1_kernel() {
    __shared__ double sh0[RED_TPB], sh1[RED_TPB], sh2[RED_TPB], sh3[RED_TPB];
    const int tid = threadIdx.x;
    const int blk = blockIdx.x;
    const int per_blk = BN / RED_BLKS;
    const int base = blk * per_blk;
    double c0 = 0.0, c1 = 0.0, rp = 0.0, dt = 0.0;
    for (int off = tid; off < per_blk; off += RED_TPB) {
        int idx = base + off;
        // same fmin order over sg=0..3 as R9's combine
        const float* p0 = g_cdp + (size_t)idx * SEG;
        float a0 = fminf(fminf(p0[0], p0[1]), fminf(p0[2], p0[3]));
        const float* p1 = g_cdp + (size_t)(idx + BN) * SEG;
        float a1 = fminf(fminf(p1[0], p1[1]), fminf(p1[2], p1[3]));
        c0 += (double)a0;
        c1 += (double)a1;
        rp += (double)g_rep[idx];
        float dd = g_nrm0[idx * 3 + 0] * g_nrm1[idx * 3 + 0]
                 + g_nrm0[idx * 3 + 1] * g_nrm1[idx * 3 + 1]
                 + g_nrm0[idx * 3 + 2] * g_nrm1[idx * 3 + 2];
        dt += (double)dd;
    }
    sh0[tid] = c0; sh1[tid] = c1; sh2[tid] = rp; sh3[tid] = dt;
    __syncthreads();
    for (int off = RED_TPB / 2; off > 0; off >>= 1) {
        if (tid < off) {
            sh0[tid] += sh0[tid + off];
            sh1[tid] += sh1[tid + off];
            sh2[tid] += sh2[tid + off];
            sh3[tid] += sh3[tid + off];
        }
        __syncthreads();
    }
    if (tid == 0) {
        g_part[blk][0] = sh0[0];
        g_part[blk][1] = sh1[0];
        g_part[blk][2] = sh2[0];
        g_part[blk][3] = sh3[0];
    }
}

__global__ void __launch_bounds__(RED_BLKS) reduce_stage2_kernel(float* __restrict__ out) {
    __shared__ double sh0[RED_BLKS], sh1[RED_BLKS], sh2[RED_BLKS], sh3[RED_BLKS];
    const int tid = threadIdx.x;
    sh0[tid] = g_part[tid][0];
    sh1[tid] = g_part[tid][1];
    sh2[tid] = g_part[tid][2];
    sh3[tid] = g_part[tid][3];
    __syncthreads();
    for (int off = RED_BLKS / 2; off > 0; off >>= 1) {
        if (tid < off) {
            sh0[tid] += sh0[tid + off];
            sh1[tid] += sh1[tid + off];
            sh2[tid] += sh2[tid + off];
            sh3[tid] += sh3[tid + off];
        }
        __syncthreads();
    }
    if (tid == 0) {
        const double inv = 1.0 / (double)BN;
        double cd    = (sh0[0] + sh1[0]) * inv;
        double rep   = sh2[0] / ((double)BN * 4.0);
        double normc = 1.0 - sh3[0] * inv;
        out[0] = (float)(cd + 0.1 * rep + 0.01 * normc);
    }
}

extern "C" void kernel_launch(void* const* d_in, const int* in_sizes, int n_in,
                              void* d_out, int out_size) {
    const float* pred = (const float*)d_in[0];
    const float* gt   = (const float*)d_in[1];
    cudaFuncSetAttribute(mega_kernel,
                         cudaFuncAttributeMaxDynamicSharedMemorySize, MEGA_SMEM);
    dim3 grid_seg(NPTS / TPB, BATCH, 2 * SEG);
    dim3 grid_mega(NPTS / TPB, BATCH, 2 + 2 * SEG);  // z 0-1: extract, z 2-9: chamfer
    count_kernel<<<grid_seg, TPB>>>(pred, gt);
    combine_kernel<<<NPTS2 / 256, 256>>>();
    collect_kernel<<<grid_seg, TPB>>>(pred, gt);
    mega_kernel<<<grid_mega, TPB, MEGA_SMEM>>>(pred, gt);
    reduce_stage1_kernel<<<RED_BLKS, RED_TPB>>>();
    reduce_stage2_kernel<<<1, RED_BLKS>>>((float*)d_out);
}